// round 2
// baseline (speedup 1.0000x reference)
#include <cuda_runtime.h>
#include <math.h>

#define BB   32
#define LL   512
#define HH   256
#define NH   8
#define HD   32
#define ITERS 6
#define E_DIM 300
#define LY   513  /* 1 + L */

// ---------------- scratch (device globals; no allocation) ----------------
__device__ float g_nodes[BB*LL*HH];
__device__ float g_nln  [BB*LL*HH];
__device__ float g_q    [BB*LL*HH];
__device__ float g_k    [BB*LL*HH];
__device__ float g_att  [BB*LL*HH];
__device__ float g_yk   [BB*LY*HH];
__device__ float g_yv   [BB*LY*HH];
__device__ float g_relay[BB*HH];
__device__ float g_ak   [BB*HH];
__device__ float g_av   [BB*HH];
__device__ float g_q2   [BB*HH];
__device__ float g_att2 [BB*HH];

// ---------------- helpers ----------------
__device__ __forceinline__ float warpReduceSum(float v) {
#pragma unroll
    for (int o = 16; o > 0; o >>= 1) v += __shfl_xor_sync(0xffffffffu, v, o);
    return v;
}

// ---------------- generic SGEMM: C[M x 256] = gather(A)[M x K] @ W[K x 256] (+epilogue)
// amode: 0 = plain A
//        1 = embedding gather: A[row,kk] = emb[data[row]*300 + kk]
//        2 = y gather: row -> (b=row/513, j=row%513); j==0 ? relay[b] : nodes[b, j-1]
// emode: 0 = +bias
//        1 = +bias + pos_emb[row % 512]
//        2 = C[row] += leaky_relu(acc + bias)   (residual accumulate into C)
__global__ void __launch_bounds__(256)
gemm_kernel(const float* __restrict__ A, const float* __restrict__ W,
            const float* __restrict__ bias, float* __restrict__ C,
            int M, int K, int amode, int emode,
            const int* __restrict__ data, const float* __restrict__ emb,
            const float* __restrict__ pos,
            const float* __restrict__ relay, const float* __restrict__ nodes)
{
    const int BM = 64, BN = 64, BK = 16;
    __shared__ float As[BK][BM + 1];
    __shared__ float Bs[BK][BN];
    int tid = threadIdx.x;
    int m0 = blockIdx.y * BM;
    int n0 = blockIdx.x * BN;
    int ty = tid >> 4, tx = tid & 15;

    float acc[4][4] = {};
    int ntiles = (K + BK - 1) / BK;
    for (int kt = 0; kt < ntiles; kt++) {
        int k0 = kt * BK;
        // load A tile (1024 elems, 4 per thread), store transposed
#pragma unroll
        for (int i = 0; i < 4; i++) {
            int idx = tid + i * 256;
            int r = idx >> 4, c = idx & 15;
            int row = m0 + r, kk = k0 + c;
            float v = 0.f;
            if (row < M && kk < K) {
                if (amode == 0)      v = A[row * K + kk];
                else if (amode == 1) v = emb[data[row] * E_DIM + kk];
                else {
                    int b = row / LY, j = row - b * LY;
                    v = (j == 0) ? relay[b * HH + kk]
                                 : nodes[(b * LL + j - 1) * HH + kk];
                }
            }
            As[c][r] = v;
        }
        // load B tile (coalesced)
#pragma unroll
        for (int i = 0; i < 4; i++) {
            int idx = tid + i * 256;
            int r = idx >> 6, c = idx & 63;
            int kk = k0 + r;
            Bs[r][c] = (kk < K) ? W[kk * HH + n0 + c] : 0.f;
        }
        __syncthreads();
#pragma unroll
        for (int kk = 0; kk < BK; kk++) {
            float a[4], b4[4];
#pragma unroll
            for (int i = 0; i < 4; i++) a[i]  = As[kk][ty * 4 + i];
#pragma unroll
            for (int j = 0; j < 4; j++) b4[j] = Bs[kk][tx * 4 + j];
#pragma unroll
            for (int i = 0; i < 4; i++)
#pragma unroll
                for (int j = 0; j < 4; j++)
                    acc[i][j] += a[i] * b4[j];
        }
        __syncthreads();
    }
#pragma unroll
    for (int i = 0; i < 4; i++) {
        int row = m0 + ty * 4 + i;
        if (row >= M) continue;
#pragma unroll
        for (int j = 0; j < 4; j++) {
            int col = n0 + tx * 4 + j;
            float v = acc[i][j] + bias[col];
            if (emode == 1) {
                v += pos[(row & (LL - 1)) * HH + col];
            } else if (emode == 2) {
                float lr = v > 0.f ? v : 0.01f * v;
                v = C[row * HH + col] + lr;
            }
            C[row * HH + col] = v;
        }
    }
}

// ---------------- layernorm (one 256-thread block per row) ----------------
__global__ void __launch_bounds__(256)
layernorm_kernel(const float* __restrict__ x, float* __restrict__ y,
                 const float* __restrict__ g, const float* __restrict__ b)
{
    __shared__ float sh[8];
    int row = blockIdx.x, t = threadIdx.x;
    float v = x[row * HH + t];
    float s = warpReduceSum(v);
    if ((t & 31) == 0) sh[t >> 5] = s;
    __syncthreads();
    float mean = 0.f;
#pragma unroll
    for (int i = 0; i < 8; i++) mean += sh[i];
    mean *= (1.f / HH);
    __syncthreads();
    float d = v - mean;
    float s2 = warpReduceSum(d * d);
    if ((t & 31) == 0) sh[t >> 5] = s2;
    __syncthreads();
    float var = 0.f;
#pragma unroll
    for (int i = 0; i < 8; i++) var += sh[i];
    var *= (1.f / HH);
    y[row * HH + t] = g[t] * d * rsqrtf(var + 1e-5f) + b[t];
}

// ---------------- relay = mean over L ----------------
__global__ void relay_mean_kernel(const float* __restrict__ x0, float* __restrict__ relay)
{
    int b = blockIdx.x, t = threadIdx.x;
    float s = 0.f;
    for (int l = 0; l < LL; l++) s += x0[(b * LL + l) * HH + t];
    relay[b * HH + t] = s * (1.f / LL);
}

// ---------------- small row projection: out[b] = in[b] @ W + bias ----------------
__global__ void rowproj_kernel(const float* __restrict__ in, const float* __restrict__ W,
                               const float* __restrict__ bias, float* __restrict__ out,
                               int lrelu)
{
    __shared__ float xin[HH];
    int b = blockIdx.x, t = threadIdx.x;
    xin[t] = in[b * HH + t];
    __syncthreads();
    float s = bias[t];
#pragma unroll 8
    for (int k = 0; k < HH; k++) s += xin[k] * W[k * HH + t];
    if (lrelu) s = s > 0.f ? s : 0.01f * s;
    out[b * HH + t] = s;
}

// ---------------- msa1 windowed attention (window 3 + relay; vals from K!) ----------
__global__ void __launch_bounds__(256)
msa1_attn_kernel(const float* __restrict__ q, const float* __restrict__ k,
                 const float* __restrict__ ak, const float* __restrict__ av,
                 float* __restrict__ att)
{
    int row = blockIdx.x;                 // b*L + l
    int b = row >> 9, l = row & (LL - 1);
    int t = threadIdx.x, d = t & 31;
    int c = ((t >> 5) * HD) + d;          // channel = h*32 + d
    float qv  = q[row * HH + c];
    float k0v = k[row * HH + c];
    float kmv = (l > 0)      ? k[(row - 1) * HH + c] : 0.f;
    float kpv = (l < LL - 1) ? k[(row + 1) * HH + c] : 0.f;
    float akv = ak[b * HH + c];
    float avv = av[b * HH + c];
    const float sc = 0.17677669529663687f;  // 1/sqrt(32)
    float s0 = warpReduceSum(qv * akv) * sc;
    float s1 = warpReduceSum(qv * kmv) * sc;
    float s2 = warpReduceSum(qv * k0v) * sc;
    float s3 = warpReduceSum(qv * kpv) * sc;
    float m = fmaxf(fmaxf(s0, s1), fmaxf(s2, s3));
    float e0 = expf(s0 - m), e1 = expf(s1 - m), e2 = expf(s2 - m), e3 = expf(s3 - m);
    float inv = 1.f / (e0 + e1 + e2 + e3);
    // faithful to source: window VALUES are the K vectors
    att[row * HH + c] = (e0 * avv + e1 * kmv + e2 * k0v + e3 * kpv) * inv;
}

// ---------------- msa2: relay attends over [relay; nodes] (513 keys) ---------------
__global__ void __launch_bounds__(256)
msa2_attn_kernel(const float* __restrict__ q2, const float* __restrict__ yk,
                 const float* __restrict__ yv, float* __restrict__ att2)
{
    __shared__ float sc[LY];
    __shared__ float red[8];
    __shared__ float part[8][HD];
    int b = blockIdx.x >> 3, h = blockIdx.x & 7;
    int t = threadIdx.x, w = t >> 5, d = t & 31;
    const float scale = 0.17677669529663687f;
    float qv = q2[b * HH + h * HD + d];
    const float* kb = yk + (size_t)b * LY * HH + h * HD;
    const float* vb = yv + (size_t)b * LY * HH + h * HD;
    for (int l = w; l < LY; l += 8) {
        float s = warpReduceSum(qv * kb[l * HH + d]) * scale;
        if (d == 0) sc[l] = s;
    }
    __syncthreads();
    // block max
    float m = -3.4e38f;
    for (int l = t; l < LY; l += 256) m = fmaxf(m, sc[l]);
#pragma unroll
    for (int o = 16; o > 0; o >>= 1) m = fmaxf(m, __shfl_xor_sync(0xffffffffu, m, o));
    if (d == 0) red[w] = m;
    __syncthreads();
    float mm = red[0];
#pragma unroll
    for (int i = 1; i < 8; i++) mm = fmaxf(mm, red[i]);
    __syncthreads();
    // exp + sum
    float ssum = 0.f;
    for (int l = t; l < LY; l += 256) { float e = expf(sc[l] - mm); sc[l] = e; ssum += e; }
    ssum = warpReduceSum(ssum);
    if (d == 0) red[w] = ssum;
    __syncthreads();
    float tot = 0.f;
#pragma unroll
    for (int i = 0; i < 8; i++) tot += red[i];
    // weighted value sum
    float acc = 0.f;
    for (int l = w; l < LY; l += 8) acc += sc[l] * vb[l * HH + d];
    part[w][d] = acc;
    __syncthreads();
    if (w == 0) {
        float o = 0.f;
#pragma unroll
        for (int i = 0; i < 8; i++) o += part[i][d];
        att2[b * HH + h * HD + d] = o / tot;
    }
}

// ---------------- mask: zero node rows where token == 1 ----------------
__global__ void mask_kernel(const int* __restrict__ data, float* __restrict__ nodes)
{
    int row = blockIdx.x;
    if (data[row] == 1) nodes[row * HH + threadIdx.x] = 0.f;
}

// ---------------- final: 0.5*max_l(nodes) + 0.5*relay ----------------
__global__ void final_kernel(const float* __restrict__ nodes, const float* __restrict__ relay,
                             float* __restrict__ out)
{
    int b = blockIdx.x, t = threadIdx.x;
    float m = -3.4e38f;
    for (int l = 0; l < LL; l++) m = fmaxf(m, nodes[(b * LL + l) * HH + t]);
    out[b * HH + t] = 0.5f * m + 0.5f * relay[b * HH + t];
}

// ---------------- host ----------------
extern "C" void kernel_launch(void* const* d_in, const int* in_sizes, int n_in,
                              void* d_out, int out_size)
{
    const int*   data     = (const int*)  d_in[0];
    const float* emb      = (const float*)d_in[1];
    const float* emb_fc_W = (const float*)d_in[2];
    const float* emb_fc_b = (const float*)d_in[3];
    const float* pos_emb  = (const float*)d_in[4];
    const float* ln_g     = (const float*)d_in[5];
    const float* ln_b     = (const float*)d_in[6];
    const float* r_WQ = (const float*)d_in[7];
    const float* r_bQ = (const float*)d_in[8];
    const float* r_WK = (const float*)d_in[9];
    const float* r_bK = (const float*)d_in[10];
    const float* r_WV = (const float*)d_in[11];
    const float* r_bV = (const float*)d_in[12];
    const float* r_WO = (const float*)d_in[13];
    const float* r_bO = (const float*)d_in[14];
    const float* s_WQ = (const float*)d_in[15];
    const float* s_bQ = (const float*)d_in[16];
    const float* s_WK = (const float*)d_in[17];
    const float* s_bK = (const float*)d_in[18];
    const float* s_WV = (const float*)d_in[19];
    const float* s_bV = (const float*)d_in[20];
    const float* s_WO = (const float*)d_in[21];
    const float* s_bO = (const float*)d_in[22];
    float* out = (float*)d_out;
    (void)in_sizes; (void)n_in; (void)out_size;

    float *nodes, *nln, *q, *k, *att, *yk, *yv, *relay, *ak, *av, *q2, *att2;
    cudaGetSymbolAddress((void**)&nodes, g_nodes);
    cudaGetSymbolAddress((void**)&nln,   g_nln);
    cudaGetSymbolAddress((void**)&q,     g_q);
    cudaGetSymbolAddress((void**)&k,     g_k);
    cudaGetSymbolAddress((void**)&att,   g_att);
    cudaGetSymbolAddress((void**)&yk,    g_yk);
    cudaGetSymbolAddress((void**)&yv,    g_yv);
    cudaGetSymbolAddress((void**)&relay, g_relay);
    cudaGetSymbolAddress((void**)&ak,    g_ak);
    cudaGetSymbolAddress((void**)&av,    g_av);
    cudaGetSymbolAddress((void**)&q2,    g_q2);
    cudaGetSymbolAddress((void**)&att2,  g_att2);

    const int M1 = BB * LL;    // 16384
    const int M2 = BB * LY;    // 16416
    dim3 blk(256);
    dim3 gg1(4, (M1 + 63) / 64);
    dim3 gg2(4, (M2 + 63) / 64);

    // x0 = emb[data] @ emb_fc_W + b + pos ; relay = mean_L(x0)
    gemm_kernel<<<gg1, blk>>>(nullptr, emb_fc_W, emb_fc_b, nodes, M1, E_DIM, 1, 1,
                              data, emb, pos_emb, nullptr, nullptr);
    relay_mean_kernel<<<BB, HH>>>(nodes, relay);

    for (int i = 0; i < ITERS; i++) {
        const float* WQ = r_WQ + i * HH * HH; const float* bQ = r_bQ + i * HH;
        const float* WK = r_WK + i * HH * HH; const float* bK = r_bK + i * HH;
        const float* WV = r_WV + i * HH * HH; const float* bV = r_bV + i * HH;
        const float* WO = r_WO + i * HH * HH; const float* bO = r_bO + i * HH;
        const float* sWQ = s_WQ + i * HH * HH; const float* sbQ = s_bQ + i * HH;
        const float* sWK = s_WK + i * HH * HH; const float* sbK = s_bK + i * HH;
        const float* sWV = s_WV + i * HH * HH; const float* sbV = s_bV + i * HH;
        const float* sWO = s_WO + i * HH * HH; const float* sbO = s_bO + i * HH;

        layernorm_kernel<<<M1, blk>>>(nodes, nln, ln_g + i * HH, ln_b + i * HH);
        gemm_kernel<<<gg1, blk>>>(nln, WQ, bQ, q, M1, HH, 0, 0,
                                  nullptr, nullptr, nullptr, nullptr, nullptr);
        gemm_kernel<<<gg1, blk>>>(nln, WK, bK, k, M1, HH, 0, 0,
                                  nullptr, nullptr, nullptr, nullptr, nullptr);
        rowproj_kernel<<<BB, HH>>>(relay, WK, bK, ak, 0);
        rowproj_kernel<<<BB, HH>>>(relay, WV, bV, av, 0);
        msa1_attn_kernel<<<M1, blk>>>(q, k, ak, av, att);
        gemm_kernel<<<gg1, blk>>>(att, WO, bO, nodes, M1, HH, 0, 2,
                                  nullptr, nullptr, nullptr, nullptr, nullptr);
        // msa2: q2 from old relay; yk/yv over [relay; updated nodes]
        rowproj_kernel<<<BB, HH>>>(relay, sWQ, sbQ, q2, 0);
        gemm_kernel<<<gg2, blk>>>(nullptr, sWK, sbK, yk, M2, HH, 2, 0,
                                  nullptr, nullptr, nullptr, relay, nodes);
        gemm_kernel<<<gg2, blk>>>(nullptr, sWV, sbV, yv, M2, HH, 2, 0,
                                  nullptr, nullptr, nullptr, relay, nodes);
        msa2_attn_kernel<<<BB * NH, blk>>>(q2, yk, yv, att2);
        rowproj_kernel<<<BB, HH>>>(att2, sWO, sbO, relay, 1);
        mask_kernel<<<M1, blk>>>(data, nodes);
    }
    final_kernel<<<BB, HH>>>(nodes, relay, out);
}

// round 4
// speedup vs baseline: 1.5261x; 1.5261x over previous
#include <cuda_runtime.h>
#include <math.h>

#define BB   32
#define LL   512
#define HH   256
#define NH   8
#define HD   32
#define ITERS 6
#define E_DIM 300
#define LY   513  /* 1 + L */

typedef unsigned long long ull;

// ---------------- scratch (device globals; no allocation) ----------------
__device__ float g_nodes[BB*LL*HH];
__device__ float g_nln  [BB*LL*HH];
__device__ float g_q    [BB*LL*HH];
__device__ float g_k    [BB*LL*HH];
__device__ float g_att  [BB*LL*HH];
__device__ float g_yk   [BB*LY*HH];
__device__ float g_yv   [BB*LY*HH];
__device__ float g_relay[BB*HH];
__device__ float g_ak   [BB*HH];
__device__ float g_av   [BB*HH];
__device__ float g_q2   [BB*HH];
__device__ float g_att2 [BB*HH];

// ---------------- helpers ----------------
__device__ __forceinline__ float warpReduceSum(float v) {
#pragma unroll
    for (int o = 16; o > 0; o >>= 1) v += __shfl_xor_sync(0xffffffffu, v, o);
    return v;
}

__device__ __forceinline__ ull pack2(float x, float y) {
    ull r; asm("mov.b64 %0, {%1, %2};" : "=l"(r) : "f"(x), "f"(y)); return r;
}
__device__ __forceinline__ float2 unpack2(ull v) {
    float2 r; asm("mov.b64 {%0, %1}, %2;" : "=f"(r.x), "=f"(r.y) : "l"(v)); return r;
}
__device__ __forceinline__ void ffma2(ull& d, ull a, ull b) {
    asm("fma.rn.f32x2 %0, %1, %2, %0;" : "+l"(d) : "l"(a), "l"(b));
}

// ---------------- SGEMM: C[M x 256] = gather(A)[M x K] @ W[K x 256] (+epilogue)
// 128x128x16 tile, 8x8 microtile, packed f32x2 FMA.
// amode: 0 plain A | 1 embedding gather | 2 [relay;nodes] gather
// emode: 0 +bias | 1 +bias+pos | 2 C += leaky_relu(acc+bias)
// blockIdx.z == 1 -> use W2/b2/C2 (fused second GEMM sharing everything else)
__global__ void __launch_bounds__(256, 2)
gemm_kernel(const float* __restrict__ A, const float* __restrict__ W,
            const float* __restrict__ bias, float* __restrict__ C,
            int M, int K, int amode, int emode,
            const int* __restrict__ data, const float* __restrict__ emb,
            const float* __restrict__ pos,
            const float* __restrict__ relay, const float* __restrict__ nodes,
            const float* __restrict__ W2, const float* __restrict__ b2,
            float* __restrict__ C2)
{
    if (blockIdx.z == 1) { W = W2; bias = b2; C = C2; }
    __shared__ float As[16][128];
    __shared__ float Bs[16][128];
    const int tid = threadIdx.x;
    const int m0 = blockIdx.y * 128;
    const int n0 = blockIdx.x * 128;
    const int tx = tid & 15, ty = tid >> 4;
    const int rowA = tid >> 2, colA = (tid & 3) * 4;   // A tile: 64 rows/pass x 16k
    const int rowB = tid >> 5, colB = (tid & 31) * 4;  // B tile: 8 k/pass x 128n

    ull acc[8][4];
#pragma unroll
    for (int i = 0; i < 8; i++)
#pragma unroll
        for (int j = 0; j < 4; j++) acc[i][j] = 0ull;

    for (int k0 = 0; k0 < K; k0 += 16) {
        // --- load A tile (transposed into As[k][m]) ---
#pragma unroll
        for (int p = 0; p < 2; p++) {
            int r = rowA + p * 64;
            int grow = m0 + r;
            float4 v = make_float4(0.f, 0.f, 0.f, 0.f);
            if (grow < M && (k0 + colA) < K) {
                const float* src;
                if (amode == 0)      src = A + (size_t)grow * K + k0 + colA;
                else if (amode == 1) src = emb + (size_t)data[grow] * E_DIM + k0 + colA;
                else {
                    int b = grow / LY, j = grow - b * LY;
                    src = (j == 0) ? relay + b * HH + k0 + colA
                                   : nodes + (size_t)(b * LL + j - 1) * HH + k0 + colA;
                }
                v = *(const float4*)src;
            }
            As[colA + 0][r] = v.x;
            As[colA + 1][r] = v.y;
            As[colA + 2][r] = v.z;
            As[colA + 3][r] = v.w;
        }
        // --- load B tile ---
#pragma unroll
        for (int p = 0; p < 2; p++) {
            int r = rowB + p * 8;
            int gk = k0 + r;
            float4 v = make_float4(0.f, 0.f, 0.f, 0.f);
            if (gk < K) v = *(const float4*)(W + (size_t)gk * HH + n0 + colB);
            *(float4*)&Bs[r][colB] = v;
        }
        __syncthreads();
#pragma unroll
        for (int kk = 0; kk < 16; kk++) {
            float4 a0 = *(float4*)&As[kk][ty * 8];
            float4 a1 = *(float4*)&As[kk][ty * 8 + 4];
            float4 b0 = *(float4*)&Bs[kk][tx * 8];
            float4 b1 = *(float4*)&Bs[kk][tx * 8 + 4];
            ull bb[4] = { pack2(b0.x, b0.y), pack2(b0.z, b0.w),
                          pack2(b1.x, b1.y), pack2(b1.z, b1.w) };
            float av8[8] = { a0.x, a0.y, a0.z, a0.w, a1.x, a1.y, a1.z, a1.w };
#pragma unroll
            for (int i = 0; i < 8; i++) {
                ull aa = pack2(av8[i], av8[i]);
#pragma unroll
                for (int j = 0; j < 4; j++) ffma2(acc[i][j], aa, bb[j]);
            }
        }
        __syncthreads();
    }

#pragma unroll
    for (int i = 0; i < 8; i++) {
        int row = m0 + ty * 8 + i;
        if (row >= M) continue;
#pragma unroll
        for (int j = 0; j < 4; j++) {
            int col = n0 + tx * 8 + j * 2;
            float2 p = unpack2(acc[i][j]);
            float v0 = p.x + bias[col];
            float v1 = p.y + bias[col + 1];
            if (emode == 1) {
                v0 += pos[(row & (LL - 1)) * HH + col];
                v1 += pos[(row & (LL - 1)) * HH + col + 1];
            } else if (emode == 2) {
                v0 = (v0 > 0.f ? v0 : 0.01f * v0) + C[(size_t)row * HH + col];
                v1 = (v1 > 0.f ? v1 : 0.01f * v1) + C[(size_t)row * HH + col + 1];
            }
            *(float2*)&C[(size_t)row * HH + col] = make_float2(v0, v1);
        }
    }
}

// ---------------- layernorm: one warp per row ----------------
__global__ void __launch_bounds__(256)
layernorm_kernel(const float* __restrict__ x, float* __restrict__ y,
                 const float* __restrict__ g, const float* __restrict__ b)
{
    int w = threadIdx.x >> 5, lane = threadIdx.x & 31;
    int row = blockIdx.x * 8 + w;
    const float* xr = x + (size_t)row * HH;
    float4 v0 = *(const float4*)&xr[lane * 4];
    float4 v1 = *(const float4*)&xr[lane * 4 + 128];
    float s = v0.x + v0.y + v0.z + v0.w + v1.x + v1.y + v1.z + v1.w;
    float mean = warpReduceSum(s) * (1.f / HH);
    float d0 = v0.x - mean, d1 = v0.y - mean, d2 = v0.z - mean, d3 = v0.w - mean;
    float d4 = v1.x - mean, d5 = v1.y - mean, d6 = v1.z - mean, d7 = v1.w - mean;
    float s2 = d0*d0 + d1*d1 + d2*d2 + d3*d3 + d4*d4 + d5*d5 + d6*d6 + d7*d7;
    float var = warpReduceSum(s2) * (1.f / HH);
    float rs = rsqrtf(var + 1e-5f);
    float4 g0 = *(const float4*)&g[lane * 4];
    float4 g1 = *(const float4*)&g[lane * 4 + 128];
    float4 bb0 = *(const float4*)&b[lane * 4];
    float4 bb1 = *(const float4*)&b[lane * 4 + 128];
    float* yr = y + (size_t)row * HH;
    *(float4*)&yr[lane * 4] = make_float4(g0.x*d0*rs + bb0.x, g0.y*d1*rs + bb0.y,
                                          g0.z*d2*rs + bb0.z, g0.w*d3*rs + bb0.w);
    *(float4*)&yr[lane * 4 + 128] = make_float4(g1.x*d4*rs + bb1.x, g1.y*d5*rs + bb1.y,
                                                g1.z*d6*rs + bb1.z, g1.w*d7*rs + bb1.w);
}

// ---------------- relay = mean over L ----------------
__global__ void relay_mean_kernel(const float* __restrict__ x0, float* __restrict__ relay)
{
    int b = blockIdx.x, t = threadIdx.x;
    float s = 0.f;
    for (int l = 0; l < LL; l++) s += x0[(size_t)(b * LL + l) * HH + t];
    relay[b * HH + t] = s * (1.f / LL);
}

// ---------------- small row projection (two fused): out[b] = in[b] @ W + bias ------
__global__ void rowproj2_kernel(const float* __restrict__ in,
                                const float* __restrict__ W1, const float* __restrict__ b1,
                                float* __restrict__ o1,
                                const float* __restrict__ W2, const float* __restrict__ b2,
                                float* __restrict__ o2)
{
    const float* W = W1; const float* bi = b1; float* o = o1;
    int b = blockIdx.x;
    if (b >= BB) { b -= BB; W = W2; bi = b2; o = o2; }
    __shared__ float xin[HH];
    int t = threadIdx.x;
    xin[t] = in[b * HH + t];
    __syncthreads();
    float s = bi[t];
#pragma unroll 8
    for (int k = 0; k < HH; k++) s += xin[k] * W[k * HH + t];
    o[b * HH + t] = s;
}

__global__ void rowproj_kernel(const float* __restrict__ in, const float* __restrict__ W,
                               const float* __restrict__ bias, float* __restrict__ out,
                               int lrelu)
{
    __shared__ float xin[HH];
    int b = blockIdx.x, t = threadIdx.x;
    xin[t] = in[b * HH + t];
    __syncthreads();
    float s = bias[t];
#pragma unroll 8
    for (int k = 0; k < HH; k++) s += xin[k] * W[k * HH + t];
    if (lrelu) s = s > 0.f ? s : 0.01f * s;
    out[b * HH + t] = s;
}

// ---------------- msa1 windowed attention (window 3 + relay; vals from K!) ----------
__global__ void __launch_bounds__(256)
msa1_attn_kernel(const float* __restrict__ q, const float* __restrict__ k,
                 const float* __restrict__ ak, const float* __restrict__ av,
                 float* __restrict__ att)
{
    int row = blockIdx.x;                 // b*L + l
    int b = row >> 9, l = row & (LL - 1);
    int t = threadIdx.x;
    int c = t;                            // channel = h*32 + d
    float qv  = q[(size_t)row * HH + c];
    float k0v = k[(size_t)row * HH + c];
    float kmv = (l > 0)      ? k[(size_t)(row - 1) * HH + c] : 0.f;
    float kpv = (l < LL - 1) ? k[(size_t)(row + 1) * HH + c] : 0.f;
    float akv = ak[b * HH + c];
    float avv = av[b * HH + c];
    const float sc = 0.17677669529663687f;  // 1/sqrt(32)
    float s0 = warpReduceSum(qv * akv) * sc;
    float s1 = warpReduceSum(qv * kmv) * sc;
    float s2 = warpReduceSum(qv * k0v) * sc;
    float s3 = warpReduceSum(qv * kpv) * sc;
    float m = fmaxf(fmaxf(s0, s1), fmaxf(s2, s3));
    float e0 = expf(s0 - m), e1 = expf(s1 - m), e2 = expf(s2 - m), e3 = expf(s3 - m);
    float inv = 1.f / (e0 + e1 + e2 + e3);
    att[(size_t)row * HH + c] = (e0 * avv + e1 * kmv + e2 * k0v + e3 * kpv) * inv;
}

// ---------------- msa2: relay attends over [relay; nodes] (513 keys) ---------------
__global__ void __launch_bounds__(256)
msa2_attn_kernel(const float* __restrict__ q2, const float* __restrict__ yk,
                 const float* __restrict__ yv, float* __restrict__ att2)
{
    __shared__ float sc[LY];
    __shared__ float red[8];
    __shared__ float part[8][HD];
    int b = blockIdx.x >> 3, h = blockIdx.x & 7;
    int t = threadIdx.x, w = t >> 5, d = t & 31;
    const float scale = 0.17677669529663687f;
    float qv = q2[b * HH + h * HD + d];
    const float* kb = yk + (size_t)b * LY * HH + h * HD;
    const float* vb = yv + (size_t)b * LY * HH + h * HD;
    for (int l = w; l < LY; l += 8) {
        float s = warpReduceSum(qv * kb[(size_t)l * HH + d]) * scale;
        if (d == 0) sc[l] = s;
    }
    __syncthreads();
    float m = -3.4e38f;
    for (int l = t; l < LY; l += 256) m = fmaxf(m, sc[l]);
#pragma unroll
    for (int o = 16; o > 0; o >>= 1) m = fmaxf(m, __shfl_xor_sync(0xffffffffu, m, o));
    if (d == 0) red[w] = m;
    __syncthreads();
    float mm = red[0];
#pragma unroll
    for (int i = 1; i < 8; i++) mm = fmaxf(mm, red[i]);
    __syncthreads();
    float ssum = 0.f;
    for (int l = t; l < LY; l += 256) { float e = expf(sc[l] - mm); sc[l] = e; ssum += e; }
    ssum = warpReduceSum(ssum);
    if (d == 0) red[w] = ssum;
    __syncthreads();
    float tot = 0.f;
#pragma unroll
    for (int i = 0; i < 8; i++) tot += red[i];
    float acc = 0.f;
    for (int l = w; l < LY; l += 8) acc += sc[l] * vb[(size_t)l * HH + d];
    part[w][d] = acc;
    __syncthreads();
    if (w == 0) {
        float o = 0.f;
#pragma unroll
        for (int i = 0; i < 8; i++) o += part[i][d];
        att2[b * HH + h * HD + d] = o / tot;
    }
}

// ---------------- mask: zero node rows where token == 1 ----------------
__global__ void mask_kernel(const int* __restrict__ data, float* __restrict__ nodes)
{
    int row = blockIdx.x * 8 + (threadIdx.x >> 5);
    if (data[row] == 1) {
        int lane = threadIdx.x & 31;
        float4 z = make_float4(0.f, 0.f, 0.f, 0.f);
        *(float4*)&nodes[(size_t)row * HH + lane * 4] = z;
        *(float4*)&nodes[(size_t)row * HH + lane * 4 + 128] = z;
    }
}

// ---------------- final: 0.5*max_l(nodes) + 0.5*relay ----------------
__global__ void final_kernel(const float* __restrict__ nodes, const float* __restrict__ relay,
                             float* __restrict__ out)
{
    int b = blockIdx.x, t = threadIdx.x;
    float m = -3.4e38f;
    for (int l = 0; l < LL; l++) m = fmaxf(m, nodes[(size_t)(b * LL + l) * HH + t]);
    out[b * HH + t] = 0.5f * m + 0.5f * relay[b * HH + t];
}

// ---------------- host ----------------
extern "C" void kernel_launch(void* const* d_in, const int* in_sizes, int n_in,
                              void* d_out, int out_size)
{
    const int*   data     = (const int*)  d_in[0];
    const float* emb      = (const float*)d_in[1];
    const float* emb_fc_W = (const float*)d_in[2];
    const float* emb_fc_b = (const float*)d_in[3];
    const float* pos_emb  = (const float*)d_in[4];
    const float* ln_g     = (const float*)d_in[5];
    const float* ln_b     = (const float*)d_in[6];
    const float* r_WQ = (const float*)d_in[7];
    const float* r_bQ = (const float*)d_in[8];
    const float* r_WK = (const float*)d_in[9];
    const float* r_bK = (const float*)d_in[10];
    const float* r_WV = (const float*)d_in[11];
    const float* r_bV = (const float*)d_in[12];
    const float* r_WO = (const float*)d_in[13];
    const float* r_bO = (const float*)d_in[14];
    const float* s_WQ = (const float*)d_in[15];
    const float* s_bQ = (const float*)d_in[16];
    const float* s_WK = (const float*)d_in[17];
    const float* s_bK = (const float*)d_in[18];
    const float* s_WV = (const float*)d_in[19];
    const float* s_bV = (const float*)d_in[20];
    const float* s_WO = (const float*)d_in[21];
    const float* s_bO = (const float*)d_in[22];
    float* out = (float*)d_out;
    (void)in_sizes; (void)n_in; (void)out_size;

    float *nodes, *nln, *q, *k, *att, *yk, *yv, *relay, *ak, *av, *q2, *att2;
    cudaGetSymbolAddress((void**)&nodes, g_nodes);
    cudaGetSymbolAddress((void**)&nln,   g_nln);
    cudaGetSymbolAddress((void**)&q,     g_q);
    cudaGetSymbolAddress((void**)&k,     g_k);
    cudaGetSymbolAddress((void**)&att,   g_att);
    cudaGetSymbolAddress((void**)&yk,    g_yk);
    cudaGetSymbolAddress((void**)&yv,    g_yv);
    cudaGetSymbolAddress((void**)&relay, g_relay);
    cudaGetSymbolAddress((void**)&ak,    g_ak);
    cudaGetSymbolAddress((void**)&av,    g_av);
    cudaGetSymbolAddress((void**)&q2,    g_q2);
    cudaGetSymbolAddress((void**)&att2,  g_att2);

    const int M1 = BB * LL;    // 16384
    const int M2 = BB * LY;    // 16416
    dim3 blk(256);
    dim3 gA (2, 128, 1);   // M1, single
    dim3 gA2(2, 128, 2);   // M1, fused pair
    dim3 gY2(2, 129, 2);   // M2, fused pair

    // x0 = emb[data] @ emb_fc_W + b + pos ; relay = mean_L(x0)
    gemm_kernel<<<gA, blk>>>(nullptr, emb_fc_W, emb_fc_b, nodes, M1, E_DIM, 1, 1,
                             data, emb, pos_emb, nullptr, nullptr,
                             nullptr, nullptr, nullptr);
    relay_mean_kernel<<<BB, HH>>>(nodes, relay);

    for (int i = 0; i < ITERS; i++) {
        const float* WQ = r_WQ + i * HH * HH; const float* bQ = r_bQ + i * HH;
        const float* WK = r_WK + i * HH * HH; const float* bK = r_bK + i * HH;
        const float* WV = r_WV + i * HH * HH; const float* bV = r_bV + i * HH;
        const float* WO = r_WO + i * HH * HH; const float* bO = r_bO + i * HH;
        const float* sWQ = s_WQ + i * HH * HH; const float* sbQ = s_bQ + i * HH;
        const float* sWK = s_WK + i * HH * HH; const float* sbK = s_bK + i * HH;
        const float* sWV = s_WV + i * HH * HH; const float* sbV = s_bV + i * HH;
        const float* sWO = s_WO + i * HH * HH; const float* sbO = s_bO + i * HH;

        layernorm_kernel<<<M1 / 8, blk>>>(nodes, nln, ln_g + i * HH, ln_b + i * HH);
        // fused Q + K projections
        gemm_kernel<<<gA2, blk>>>(nln, WQ, bQ, q, M1, HH, 0, 0,
                                  nullptr, nullptr, nullptr, nullptr, nullptr,
                                  WK, bK, k);
        // fused ak + av relay projections
        rowproj2_kernel<<<2 * BB, HH>>>(relay, WK, bK, ak, WV, bV, av);
        msa1_attn_kernel<<<M1, blk>>>(q, k, ak, av, att);
        gemm_kernel<<<gA, blk>>>(att, WO, bO, nodes, M1, HH, 0, 2,
                                 nullptr, nullptr, nullptr, nullptr, nullptr,
                                 nullptr, nullptr, nullptr);
        // msa2: q2 from old relay; yk/yv over [relay; updated nodes]
        rowproj_kernel<<<BB, HH>>>(relay, sWQ, sbQ, q2, 0);
        gemm_kernel<<<gY2, blk>>>(nullptr, sWK, sbK, yk, M2, HH, 2, 0,
                                  nullptr, nullptr, nullptr, relay, nodes,
                                  sWV, sbV, yv);
        msa2_attn_kernel<<<BB * NH, blk>>>(q2, yk, yv, att2);
        rowproj_kernel<<<BB, HH>>>(att2, sWO, sbO, relay, 1);
        mask_kernel<<<M1 / 8, blk>>>(data, nodes);
    }
    final_kernel<<<BB, HH>>>(nodes, relay, out);
}

// round 8
// speedup vs baseline: 1.9327x; 1.2665x over previous
#include <cuda_runtime.h>
#include <cuda_bf16.h>
#include <math.h>
#include <cstdint>

#define BB   32
#define LL   512
#define HH   256
#define NH   8
#define HD   32
#define ITERS 6
#define E_DIM 300
#define LY   513  /* 1 + L */

typedef unsigned long long ull;

// ---------------- scratch (device globals; no allocation) ----------------
__device__ float g_nodes[BB*LL*HH];
__device__ float g_q    [BB*LL*HH];
__device__ float g_k    [BB*LL*HH];
__device__ float g_yk   [BB*LY*HH];
__device__ float g_yv   [BB*LY*HH];
__device__ float g_relay[BB*HH];
__device__ float g_ak   [BB*HH];
__device__ float g_av   [BB*HH];
__device__ float g_q2   [BB*HH];
__device__ float g_att2 [BB*HH];
// bf16 split activations
__device__ __nv_bfloat16 g_nlnh[BB*LL*HH];
__device__ __nv_bfloat16 g_nlnl[BB*LL*HH];
__device__ __nv_bfloat16 g_atth[BB*LL*HH];
__device__ __nv_bfloat16 g_attl[BB*LL*HH];
__device__ __nv_bfloat16 g_yh  [BB*LY*HH];
__device__ __nv_bfloat16 g_yl  [BB*LY*HH];
// split-bf16 transposed weights: 30 slots of [256 n][256 k]
__device__ __nv_bfloat16 g_whi[30*65536];
__device__ __nv_bfloat16 g_wlo[30*65536];

// ---------------- helpers ----------------
__device__ __forceinline__ float warpReduceSum(float v) {
#pragma unroll
    for (int o = 16; o > 0; o >>= 1) v += __shfl_xor_sync(0xffffffffu, v, o);
    return v;
}
__device__ __forceinline__ uint32_t smem_to_u32(const void* p) {
    uint32_t a;
    asm("{ .reg .u64 t; cvta.to.shared.u64 t, %1; cvt.u32.u64 %0, t; }" : "=r"(a) : "l"(p));
    return a;
}
__device__ __forceinline__ uint32_t swz(uint32_t x) { return x ^ ((x >> 3) & 0x70); }

__device__ __forceinline__ void ldsm_x4(uint32_t* r, uint32_t addr) {
    asm volatile("ldmatrix.sync.aligned.m8n8.x4.shared.b16 {%0,%1,%2,%3}, [%4];"
                 : "=r"(r[0]), "=r"(r[1]), "=r"(r[2]), "=r"(r[3]) : "r"(addr));
}
__device__ __forceinline__ void ldsm_x2(uint32_t* r, uint32_t addr) {
    asm volatile("ldmatrix.sync.aligned.m8n8.x2.shared.b16 {%0,%1}, [%2];"
                 : "=r"(r[0]), "=r"(r[1]) : "r"(addr));
}
__device__ __forceinline__ void mma_bf16(float* c, const uint32_t* a, const uint32_t* b) {
    asm volatile("mma.sync.aligned.m16n8k16.row.col.f32.bf16.bf16.f32 "
                 "{%0,%1,%2,%3}, {%4,%5,%6,%7}, {%8,%9}, {%0,%1,%2,%3};"
                 : "+f"(c[0]), "+f"(c[1]), "+f"(c[2]), "+f"(c[3])
                 : "r"(a[0]), "r"(a[1]), "r"(a[2]), "r"(a[3]), "r"(b[0]), "r"(b[1]));
}
__device__ __forceinline__ void split_bf16(float v, __nv_bfloat16& h, __nv_bfloat16& l) {
    h = __float2bfloat16(v);
    l = __float2bfloat16(v - __bfloat162float(h));
}

// ============ HMMA split-bf16 GEMM: C[M x 256] = A[M x 256] @ W^T ============
// A given as bf16 hi/lo [M][256]; W as bf16 hi/lo [256 n][256 k].
// emode 0: C = acc + bias
// emode 2: nodes += leaky_relu(acc+bias); also write y hi/lo at row b*513+1+l
// blockIdx.z==1 -> second problem (wh1/wl1/b1/C1).
__global__ void __launch_bounds__(256, 1)
gemm_mma_kernel(const __nv_bfloat16* __restrict__ Ahi, const __nv_bfloat16* __restrict__ Alo,
                const __nv_bfloat16* __restrict__ wh0, const __nv_bfloat16* __restrict__ wl0,
                const float* __restrict__ b0, float* __restrict__ C0,
                const __nv_bfloat16* __restrict__ wh1, const __nv_bfloat16* __restrict__ wl1,
                const float* __restrict__ b1, float* __restrict__ C1,
                int M, int emode,
                __nv_bfloat16* __restrict__ yhi, __nv_bfloat16* __restrict__ ylo)
{
    extern __shared__ char smem[];
    const __nv_bfloat16* wh = wh0; const __nv_bfloat16* wl = wl0;
    const float* bias = b0; float* C = C0;
    if (blockIdx.z == 1) { wh = wh1; wl = wl1; bias = b1; C = C1; }

    const uint32_t sb = smem_to_u32(smem);
    const int A_LO = 16384, B_HI = 32768, B_LO = 49152;
    const int tid = threadIdx.x, lane = tid & 31, wid = tid >> 5;
    const int warpM = wid & 1, warpN = wid >> 1;
    const int m0 = blockIdx.y * 128, n0 = blockIdx.x * 128;

    float c[4][4][4];
#pragma unroll
    for (int i = 0; i < 4; i++)
#pragma unroll
        for (int j = 0; j < 4; j++)
#pragma unroll
            for (int l = 0; l < 4; l++) c[i][j][l] = 0.f;

    const int half = tid >> 7, r = tid & 127;

    for (int kc = 0; kc < 4; kc++) {
        const int k0 = kc << 6;
        // ---- stage A [128 rows x 64 k] hi+lo ----
        {
            int grow = m0 + r;
            bool valid = grow < M;
            const __nv_bfloat16* src = (half ? Alo : Ahi) + (size_t)grow * HH + k0;
            char* dst = smem + half * A_LO;
            uint32_t base = (uint32_t)r * 128u;
#pragma unroll
            for (int i = 0; i < 8; i++) {
                uint4 v = valid ? *(const uint4*)(src + i * 8)
                                : make_uint4(0u, 0u, 0u, 0u);
                *(uint4*)(dst + swz(base + i * 16)) = v;
            }
        }
        // ---- stage B [128 n x 64 k] hi+lo ----
        {
            const __nv_bfloat16* src = (half ? wl : wh) + (size_t)(n0 + r) * HH + k0;
            char* dst = smem + B_HI + half * 16384;
            uint32_t base = (uint32_t)r * 128u;
#pragma unroll
            for (int i = 0; i < 8; i++) {
                uint4 v = *(const uint4*)(src + i * 8);
                *(uint4*)(dst + swz(base + i * 16)) = v;
            }
        }
        __syncthreads();
#pragma unroll
        for (int ks = 0; ks < 4; ks++) {
            uint32_t ah[4][4], al[4][4];
#pragma unroll
            for (int mt = 0; mt < 4; mt++) {
                int row = warpM * 64 + mt * 16 + (lane & 15);
                uint32_t off = swz((uint32_t)row * 128u + ks * 32u + ((lane >> 4) << 4));
                ldsm_x4(ah[mt], sb + off);
                ldsm_x4(al[mt], sb + A_LO + off);
            }
            uint32_t bh[4][2], bl[4][2];
#pragma unroll
            for (int nt = 0; nt < 4; nt++) {
                int n = warpN * 32 + nt * 8 + (lane & 7);
                uint32_t off = swz((uint32_t)n * 128u + ks * 32u + (((lane >> 3) & 1) << 4));
                ldsm_x2(bh[nt], sb + B_HI + off);
                ldsm_x2(bl[nt], sb + B_LO + off);
            }
#pragma unroll
            for (int mt = 0; mt < 4; mt++)
#pragma unroll
                for (int nt = 0; nt < 4; nt++) {
                    mma_bf16(c[mt][nt], ah[mt], bh[nt]);
                    mma_bf16(c[mt][nt], ah[mt], bl[nt]);
                    mma_bf16(c[mt][nt], al[mt], bh[nt]);
                }
        }
        __syncthreads();
    }

    // ---- epilogue ----
    const int gid = lane >> 2, tig = lane & 3;
#pragma unroll
    for (int mt = 0; mt < 4; mt++)
#pragma unroll
        for (int nt = 0; nt < 4; nt++) {
            int col = n0 + warpN * 32 + nt * 8 + tig * 2;
            float bc0 = bias[col], bc1 = bias[col + 1];
#pragma unroll
            for (int h = 0; h < 2; h++) {
                int row = m0 + warpM * 64 + mt * 16 + gid + h * 8;
                if (row >= M) continue;
                float v0 = c[mt][nt][h * 2 + 0] + bc0;
                float v1 = c[mt][nt][h * 2 + 1] + bc1;
                float* crow = C + (size_t)row * HH + col;
                if (emode == 2) {
                    float l0 = v0 > 0.f ? v0 : 0.01f * v0;
                    float l1 = v1 > 0.f ? v1 : 0.01f * v1;
                    float n0v = crow[0] + l0;
                    float n1v = crow[1] + l1;
                    *(float2*)crow = make_float2(n0v, n1v);
                    int b = row >> 9, ll = row & (LL - 1);
                    size_t yo = (size_t)(b * LY + 1 + ll) * HH + col;
                    __nv_bfloat16 h0, l0b, h1, l1b;
                    split_bf16(n0v, h0, l0b);
                    split_bf16(n1v, h1, l1b);
                    *(__nv_bfloat162*)(yhi + yo) = __nv_bfloat162(h0, h1);
                    *(__nv_bfloat162*)(ylo + yo) = __nv_bfloat162(l0b, l1b);
                } else {
                    *(float2*)crow = make_float2(v0, v1);
                }
            }
        }
}

// ============ weight prep: transpose + split fp32 [K,N] -> bf16 hi/lo [N,K] ============
__global__ void prep_w_kernel(const float* __restrict__ rWQ, const float* __restrict__ rWK,
                              const float* __restrict__ rWO, const float* __restrict__ sWK,
                              const float* __restrict__ sWV,
                              __nv_bfloat16* __restrict__ whi, __nv_bfloat16* __restrict__ wlo)
{
    int slot = blockIdx.y;            // 0..29
    int fam = slot / 6, it = slot % 6;
    const float* W = (fam == 0 ? rWQ : fam == 1 ? rWK : fam == 2 ? rWO :
                      fam == 3 ? sWK : sWV) + (size_t)it * HH * HH;
    int n = blockIdx.x;
    int k = threadIdx.x;
    float x = W[(size_t)k * HH + n];
    __nv_bfloat16 h, l;
    split_bf16(x, h, l);
    size_t o = (size_t)slot * 65536 + (size_t)n * HH + k;
    whi[o] = h; wlo[o] = l;
}

// ============ SIMT GEMM (embedding projection, K=300, f32x2) ============
__device__ __forceinline__ ull pack2(float x, float y) {
    ull r; asm("mov.b64 %0, {%1, %2};" : "=l"(r) : "f"(x), "f"(y)); return r;
}
__device__ __forceinline__ float2 unpack2(ull v) {
    float2 r; asm("mov.b64 {%0, %1}, %2;" : "=f"(r.x), "=f"(r.y) : "l"(v)); return r;
}
__device__ __forceinline__ void ffma2(ull& d, ull a, ull b) {
    asm("fma.rn.f32x2 %0, %1, %2, %0;" : "+l"(d) : "l"(a), "l"(b));
}
__global__ void __launch_bounds__(256, 2)
gemm_kernel(const float* __restrict__ W, const float* __restrict__ bias,
            float* __restrict__ C, int M, int K,
            const int* __restrict__ data, const float* __restrict__ emb,
            const float* __restrict__ pos)
{
    __shared__ float As[16][128];
    __shared__ float Bs[16][128];
    const int tid = threadIdx.x;
    const int m0 = blockIdx.y * 128;
    const int n0 = blockIdx.x * 128;
    const int tx = tid & 15, ty = tid >> 4;
    const int rowA = tid >> 2, colA = (tid & 3) * 4;
    const int rowB = tid >> 5, colB = (tid & 31) * 4;

    ull acc[8][4];
#pragma unroll
    for (int i = 0; i < 8; i++)
#pragma unroll
        for (int j = 0; j < 4; j++) acc[i][j] = 0ull;

    for (int k0 = 0; k0 < K; k0 += 16) {
#pragma unroll
        for (int p = 0; p < 2; p++) {
            int r = rowA + p * 64;
            int grow = m0 + r;
            float4 v = make_float4(0.f, 0.f, 0.f, 0.f);
            if (grow < M && (k0 + colA) < K)
                v = *(const float4*)(emb + (size_t)data[grow] * E_DIM + k0 + colA);
            As[colA + 0][r] = v.x; As[colA + 1][r] = v.y;
            As[colA + 2][r] = v.z; As[colA + 3][r] = v.w;
        }
#pragma unroll
        for (int p = 0; p < 2; p++) {
            int r = rowB + p * 8;
            int gk = k0 + r;
            float4 v = make_float4(0.f, 0.f, 0.f, 0.f);
            if (gk < K) v = *(const float4*)(W + (size_t)gk * HH + n0 + colB);
            *(float4*)&Bs[r][colB] = v;
        }
        __syncthreads();
#pragma unroll
        for (int kk = 0; kk < 16; kk++) {
            float4 a0 = *(float4*)&As[kk][ty * 8];
            float4 a1 = *(float4*)&As[kk][ty * 8 + 4];
            float4 b0 = *(float4*)&Bs[kk][tx * 8];
            float4 b1 = *(float4*)&Bs[kk][tx * 8 + 4];
            ull bb[4] = { pack2(b0.x, b0.y), pack2(b0.z, b0.w),
                          pack2(b1.x, b1.y), pack2(b1.z, b1.w) };
            float av8[8] = { a0.x, a0.y, a0.z, a0.w, a1.x, a1.y, a1.z, a1.w };
#pragma unroll
            for (int i = 0; i < 8; i++) {
                ull aa = pack2(av8[i], av8[i]);
#pragma unroll
                for (int j = 0; j < 4; j++) ffma2(acc[i][j], aa, bb[j]);
            }
        }
        __syncthreads();
    }
#pragma unroll
    for (int i = 0; i < 8; i++) {
        int row = m0 + ty * 8 + i;
        if (row >= M) continue;
#pragma unroll
        for (int j = 0; j < 4; j++) {
            int col = n0 + tx * 8 + j * 2;
            float2 p = unpack2(acc[i][j]);
            float v0 = p.x + bias[col]     + pos[(row & (LL - 1)) * HH + col];
            float v1 = p.y + bias[col + 1] + pos[(row & (LL - 1)) * HH + col + 1];
            *(float2*)&C[(size_t)row * HH + col] = make_float2(v0, v1);
        }
    }
}

// ---------------- layernorm: one warp per row -> split bf16 out ----------------
__global__ void __launch_bounds__(256)
layernorm_kernel(const float* __restrict__ x,
                 __nv_bfloat16* __restrict__ yh, __nv_bfloat16* __restrict__ yl,
                 const float* __restrict__ g, const float* __restrict__ b)
{
    int w = threadIdx.x >> 5, lane = threadIdx.x & 31;
    int row = blockIdx.x * 8 + w;
    const float* xr = x + (size_t)row * HH;
    float4 v0 = *(const float4*)&xr[lane * 4];
    float4 v1 = *(const float4*)&xr[lane * 4 + 128];
    float s = v0.x + v0.y + v0.z + v0.w + v1.x + v1.y + v1.z + v1.w;
    float mean = warpReduceSum(s) * (1.f / HH);
    float d[8] = { v0.x - mean, v0.y - mean, v0.z - mean, v0.w - mean,
                   v1.x - mean, v1.y - mean, v1.z - mean, v1.w - mean };
    float s2 = 0.f;
#pragma unroll
    for (int i = 0; i < 8; i++) s2 += d[i] * d[i];
    float var = warpReduceSum(s2) * (1.f / HH);
    float rs = rsqrtf(var + 1e-5f);
    float4 g0 = *(const float4*)&g[lane * 4];
    float4 g1 = *(const float4*)&g[lane * 4 + 128];
    float4 bb0 = *(const float4*)&b[lane * 4];
    float4 bb1 = *(const float4*)&b[lane * 4 + 128];
    float o[8] = { g0.x*d[0]*rs + bb0.x, g0.y*d[1]*rs + bb0.y,
                   g0.z*d[2]*rs + bb0.z, g0.w*d[3]*rs + bb0.w,
                   g1.x*d[4]*rs + bb1.x, g1.y*d[5]*rs + bb1.y,
                   g1.z*d[6]*rs + bb1.z, g1.w*d[7]*rs + bb1.w };
#pragma unroll
    for (int seg = 0; seg < 2; seg++) {
        ushort4 hv, lv;
        __nv_bfloat16 h, l;
        split_bf16(o[seg*4+0], h, l); hv.x = __bfloat16_as_ushort(h); lv.x = __bfloat16_as_ushort(l);
        split_bf16(o[seg*4+1], h, l); hv.y = __bfloat16_as_ushort(h); lv.y = __bfloat16_as_ushort(l);
        split_bf16(o[seg*4+2], h, l); hv.z = __bfloat16_as_ushort(h); lv.z = __bfloat16_as_ushort(l);
        split_bf16(o[seg*4+3], h, l); hv.w = __bfloat16_as_ushort(h); lv.w = __bfloat16_as_ushort(l);
        size_t off = (size_t)row * HH + lane * 4 + seg * 128;
        *(ushort4*)(yh + off) = hv;
        *(ushort4*)(yl + off) = lv;
    }
}

// ---------------- relay = mean over L ----------------
__global__ void relay_mean_kernel(const float* __restrict__ x0, float* __restrict__ relay)
{
    int b = blockIdx.x, t = threadIdx.x;
    float s = 0.f;
    for (int l = 0; l < LL; l++) s += x0[(size_t)(b * LL + l) * HH + t];
    relay[b * HH + t] = s * (1.f / LL);
}

// ---------------- relay row into y (bf16 split) ----------------
__global__ void relay_to_y_kernel(const float* __restrict__ relay,
                                  __nv_bfloat16* __restrict__ yh, __nv_bfloat16* __restrict__ yl)
{
    int b = blockIdx.x, t = threadIdx.x;
    __nv_bfloat16 h, l;
    split_bf16(relay[b * HH + t], h, l);
    size_t o = (size_t)(b * LY) * HH + t;
    yh[o] = h; yl[o] = l;
}

// ---------------- small row projections ----------------
__global__ void rowproj2_kernel(const float* __restrict__ in,
                                const float* __restrict__ W1, const float* __restrict__ b1,
                                float* __restrict__ o1,
                                const float* __restrict__ W2, const float* __restrict__ b2,
                                float* __restrict__ o2)
{
    const float* W = W1; const float* bi = b1; float* o = o1;
    int b = blockIdx.x;
    if (b >= BB) { b -= BB; W = W2; bi = b2; o = o2; }
    __shared__ float xin[HH];
    int t = threadIdx.x;
    xin[t] = in[b * HH + t];
    __syncthreads();
    float s = bi[t];
#pragma unroll 8
    for (int k = 0; k < HH; k++) s += xin[k] * W[k * HH + t];
    o[b * HH + t] = s;
}

__global__ void rowproj_kernel(const float* __restrict__ in, const float* __restrict__ W,
                               const float* __restrict__ bias, float* __restrict__ out,
                               int lrelu)
{
    __shared__ float xin[HH];
    int b = blockIdx.x, t = threadIdx.x;
    xin[t] = in[b * HH + t];
    __syncthreads();
    float s = bias[t];
#pragma unroll 8
    for (int k = 0; k < HH; k++) s += xin[k] * W[k * HH + t];
    if (lrelu) s = s > 0.f ? s : 0.01f * s;
    out[b * HH + t] = s;
}

// ---------------- msa1 windowed attention -> split bf16 att ----------------
__global__ void __launch_bounds__(256)
msa1_attn_kernel(const float* __restrict__ q, const float* __restrict__ k,
                 const float* __restrict__ ak, const float* __restrict__ av,
                 __nv_bfloat16* __restrict__ atth, __nv_bfloat16* __restrict__ attl)
{
    int row = blockIdx.x;
    int b = row >> 9, l = row & (LL - 1);
    int t = threadIdx.x;
    int c = t;
    float qv  = q[(size_t)row * HH + c];
    float k0v = k[(size_t)row * HH + c];
    float kmv = (l > 0)      ? k[(size_t)(row - 1) * HH + c] : 0.f;
    float kpv = (l < LL - 1) ? k[(size_t)(row + 1) * HH + c] : 0.f;
    float akv = ak[b * HH + c];
    float avv = av[b * HH + c];
    const float sc = 0.17677669529663687f;
    float s0 = warpReduceSum(qv * akv) * sc;
    float s1 = warpReduceSum(qv * kmv) * sc;
    float s2 = warpReduceSum(qv * k0v) * sc;
    float s3 = warpReduceSum(qv * kpv) * sc;
    float m = fmaxf(fmaxf(s0, s1), fmaxf(s2, s3));
    float e0 = expf(s0 - m), e1 = expf(s1 - m), e2 = expf(s2 - m), e3 = expf(s3 - m);
    float inv = 1.f / (e0 + e1 + e2 + e3);
    float o = (e0 * avv + e1 * kmv + e2 * k0v + e3 * kpv) * inv;
    __nv_bfloat16 h, lo;
    split_bf16(o, h, lo);
    atth[(size_t)row * HH + c] = h;
    attl[(size_t)row * HH + c] = lo;
}

// ---------------- msa2 ----------------
__global__ void __launch_bounds__(256)
msa2_attn_kernel(const float* __restrict__ q2, const float* __restrict__ yk,
                 const float* __restrict__ yv, float* __restrict__ att2)
{
    __shared__ float sc[LY];
    __shared__ float red[8];
    __shared__ float part[8][HD];
    int b = blockIdx.x >> 3, h = blockIdx.x & 7;
    int t = threadIdx.x, w = t >> 5, d = t & 31;
    const float scale = 0.17677669529663687f;
    float qv = q2[b * HH + h * HD + d];
    const float* kb = yk + (size_t)b * LY * HH + h * HD;
    const float* vb = yv + (size_t)b * LY * HH + h * HD;
    for (int l = w; l < LY; l += 8) {
        float s = warpReduceSum(qv * kb[(size_t)l * HH + d]) * scale;
        if (d == 0) sc[l] = s;
    }
    __syncthreads();
    float m = -3.4e38f;
    for (int l = t; l < LY; l += 256) m = fmaxf(m, sc[l]);
#pragma unroll
    for (int o = 16; o > 0; o >>= 1) m = fmaxf(m, __shfl_xor_sync(0xffffffffu, m, o));
    if (d == 0) red[w] = m;
    __syncthreads();
    float mm = red[0];
#pragma unroll
    for (int i = 1; i < 8; i++) mm = fmaxf(mm, red[i]);
    __syncthreads();
    float ssum = 0.f;
    for (int l = t; l < LY; l += 256) { float e = expf(sc[l] - mm); sc[l] = e; ssum += e; }
    ssum = warpReduceSum(ssum);
    if (d == 0) red[w] = ssum;
    __syncthreads();
    float tot = 0.f;
#pragma unroll
    for (int i = 0; i < 8; i++) tot += red[i];
    float acc = 0.f;
    for (int l = w; l < LY; l += 8) acc += sc[l] * vb[(size_t)l * HH + d];
    part[w][d] = acc;
    __syncthreads();
    if (w == 0) {
        float o = 0.f;
#pragma unroll
        for (int i = 0; i < 8; i++) o += part[i][d];
        att2[b * HH + h * HD + d] = o / tot;
    }
}

// ---------------- mask ----------------
__global__ void mask_kernel(const int* __restrict__ data, float* __restrict__ nodes)
{
    int row = blockIdx.x * 8 + (threadIdx.x >> 5);
    if (data[row] == 1) {
        int lane = threadIdx.x & 31;
        float4 z = make_float4(0.f, 0.f, 0.f, 0.f);
        *(float4*)&nodes[(size_t)row * HH + lane * 4] = z;
        *(float4*)&nodes[(size_t)row * HH + lane * 4 + 128] = z;
    }
}

// ---------------- final ----------------
__global__ void final_kernel(const float* __restrict__ nodes, const float* __restrict__ relay,
                             float* __restrict__ out)
{
    int b = blockIdx.x, t = threadIdx.x;
    float m = -3.4e38f;
    for (int l = 0; l < LL; l++) m = fmaxf(m, nodes[(size_t)(b * LL + l) * HH + t]);
    out[b * HH + t] = 0.5f * m + 0.5f * relay[b * HH + t];
}

// ---------------- host ----------------
extern "C" void kernel_launch(void* const* d_in, const int* in_sizes, int n_in,
                              void* d_out, int out_size)
{
    const int*   data     = (const int*)  d_in[0];
    const float* emb      = (const float*)d_in[1];
    const float* emb_fc_W = (const float*)d_in[2];
    const float* emb_fc_b = (const float*)d_in[3];
    const float* pos_emb  = (const float*)d_in[4];
    const float* ln_g     = (const float*)d_in[5];
    const float* ln_b     = (const float*)d_in[6];
    const float* r_WQ = (const float*)d_in[7];
    const float* r_bQ = (const float*)d_in[8];
    const float* r_WK = (const float*)d_in[9];
    const float* r_bK = (const float*)d_in[10];
    const float* r_WV = (const float*)d_in[11];
    const float* r_bV = (const float*)d_in[12];
    const float* r_WO = (const float*)d_in[13];
    const float* r_bO = (const float*)d_in[14];
    const float* s_WQ = (const float*)d_in[15];
    const float* s_bQ = (const float*)d_in[16];
    const float* s_WK = (const float*)d_in[17];
    const float* s_bK = (const float*)d_in[18];
    const float* s_WV = (const float*)d_in[19];
    const float* s_bV = (const float*)d_in[20];
    const float* s_WO = (const float*)d_in[21];
    const float* s_bO = (const float*)d_in[22];
    float* out = (float*)d_out;
    (void)in_sizes; (void)n_in; (void)out_size;

    float *nodes, *q, *k, *yk, *yv, *relay, *ak, *av, *q2, *att2;
    __nv_bfloat16 *whi, *wlo, *nlnh, *nlnl, *atth, *attl, *yh, *yl;
    cudaGetSymbolAddress((void**)&nodes, g_nodes);
    cudaGetSymbolAddress((void**)&q,     g_q);
    cudaGetSymbolAddress((void**)&k,     g_k);
    cudaGetSymbolAddress((void**)&yk,    g_yk);
    cudaGetSymbolAddress((void**)&yv,    g_yv);
    cudaGetSymbolAddress((void**)&relay, g_relay);
    cudaGetSymbolAddress((void**)&ak,    g_ak);
    cudaGetSymbolAddress((void**)&av,    g_av);
    cudaGetSymbolAddress((void**)&q2,    g_q2);
    cudaGetSymbolAddress((void**)&att2,  g_att2);
    cudaGetSymbolAddress((void**)&whi,   g_whi);
    cudaGetSymbolAddress((void**)&wlo,   g_wlo);
    cudaGetSymbolAddress((void**)&nlnh,  g_nlnh);
    cudaGetSymbolAddress((void**)&nlnl,  g_nlnl);
    cudaGetSymbolAddress((void**)&atth,  g_atth);
    cudaGetSymbolAddress((void**)&attl,  g_attl);
    cudaGetSymbolAddress((void**)&yh,    g_yh);
    cudaGetSymbolAddress((void**)&yl,    g_yl);

    const int M1 = BB * LL;    // 16384
    const int M2 = BB * LY;    // 16416
    const int MMA_SMEM = 65536;
    static int attr_done = 0;
    if (!attr_done) {
        cudaFuncSetAttribute(gemm_mma_kernel,
                             cudaFuncAttributeMaxDynamicSharedMemorySize, MMA_SMEM);
        attr_done = 1;
    }

    dim3 blk(256);
    auto WH = [&](int slot) { return whi + (size_t)slot * 65536; };
    auto WL = [&](int slot) { return wlo + (size_t)slot * 65536; };

    // prep split-transposed weights (slots: Q=0..5, K=6..11, O=12..17, sK=18..23, sV=24..29)
    prep_w_kernel<<<dim3(256, 30), blk>>>(r_WQ, r_WK, r_WO, s_WK, s_WV, whi, wlo);

    // x0 = emb[data] @ emb_fc_W + b + pos ; relay = mean_L(x0)
    gemm_kernel<<<dim3(2, 128), blk>>>(emb_fc_W, emb_fc_b, nodes, M1, E_DIM,
                                       data, emb, pos_emb);
    relay_mean_kernel<<<BB, HH>>>(nodes, relay);

    for (int i = 0; i < ITERS; i++) {
        const float* bQ = r_bQ + i * HH;
        const float* bK = r_bK + i * HH;
        const float* WK = r_WK + i * HH * HH;
        const float* WV = r_WV + i * HH * HH;
        const float* bV = r_bV + i * HH;
        const float* bO = r_bO + i * HH;
        const float* sWQ = s_WQ + i * HH * HH; const float* sbQ = s_bQ + i * HH;
        const float* sbK = s_bK + i * HH;
        const float* sbV = s_bV + i * HH;
        const float* sWO = s_WO + i * HH * HH; const float* sbO = s_bO + i * HH;

        layernorm_kernel<<<M1 / 8, blk>>>(nodes, nlnh, nlnl, ln_g + i * HH, ln_b + i * HH);
        // fused Q + K projections (HMMA)
        gemm_mma_kernel<<<dim3(2, 128, 2), blk, MMA_SMEM>>>(
            nlnh, nlnl, WH(i), WL(i), bQ, q, WH(6 + i), WL(6 + i), bK, k,
            M1, 0, nullptr, nullptr);
        rowproj2_kernel<<<2 * BB, HH>>>(relay, WK, bK, ak, WV, bV, av);
        msa1_attn_kernel<<<M1, blk>>>(q, k, ak, av, atth, attl);
        relay_to_y_kernel<<<BB, HH>>>(relay, yh, yl);
        // O projection + leaky residual + y emit (HMMA)
        gemm_mma_kernel<<<dim3(2, 128, 1), blk, MMA_SMEM>>>(
            atth, attl, WH(12 + i), WL(12 + i), bO, nodes,
            nullptr, nullptr, nullptr, nullptr,
            M1, 2, yh, yl);
        rowproj_kernel<<<BB, HH>>>(relay, sWQ, sbQ, q2, 0);
        // fused yK + yV (HMMA)
        gemm_mma_kernel<<<dim3(2, 129, 2), blk, MMA_SMEM>>>(
            yh, yl, WH(18 + i), WL(18 + i), sbK, yk,
            WH(24 + i), WL(24 + i), sbV, yv,
            M2, 0, nullptr, nullptr);
        msa2_attn_kernel<<<BB * NH, blk>>>(q2, yk, yv, att2);
        rowproj_kernel<<<BB, HH>>>(att2, sWO, sbO, relay, 1);
        mask_kernel<<<M1 / 8, blk>>>(data, nodes);
    }
    final_kernel<<<BB, HH>>>(nodes, relay, out);
}

// round 9
// speedup vs baseline: 2.3270x; 1.2040x over previous
#include <cuda_runtime.h>
#include <cuda_bf16.h>
#include <math.h>
#include <cstdint>

#define BB   32
#define LL   512
#define HH   256
#define NH   8
#define HD   32
#define ITERS 6
#define E_DIM 300
#define LY   513  /* 1 + L */

typedef unsigned long long ull;

// ---------------- scratch (device globals; no allocation) ----------------
__device__ float g_nodes[BB*LL*HH];
__device__ float g_q    [BB*LL*HH];
__device__ float g_k    [BB*LL*HH];
__device__ float g_yk   [BB*LY*HH];
__device__ float g_yv   [BB*LY*HH];
__device__ float g_relay[BB*HH];
__device__ float g_ak   [BB*HH];
__device__ float g_av   [BB*HH];
__device__ float g_q2   [BB*HH];
__device__ float g_att2 [BB*HH];
// bf16 split activations
__device__ __align__(16) __nv_bfloat16 g_nlnh[BB*LL*HH];
__device__ __align__(16) __nv_bfloat16 g_nlnl[BB*LL*HH];
__device__ __align__(16) __nv_bfloat16 g_atth[BB*LL*HH];
__device__ __align__(16) __nv_bfloat16 g_attl[BB*LL*HH];
__device__ __align__(16) __nv_bfloat16 g_yh  [BB*LY*HH];
__device__ __align__(16) __nv_bfloat16 g_yl  [BB*LY*HH];
// split-bf16 transposed weights: 30 slots of [256 n][256 k]
__device__ __align__(16) __nv_bfloat16 g_whi[30*65536];
__device__ __align__(16) __nv_bfloat16 g_wlo[30*65536];
// emb_fc split-transposed: [256 n][320 k] (zero-padded k>=300)
__device__ __align__(16) __nv_bfloat16 g_whiE[256*320];
__device__ __align__(16) __nv_bfloat16 g_wloE[256*320];

// ---------------- helpers ----------------
__device__ __forceinline__ float warpReduceSum(float v) {
#pragma unroll
    for (int o = 16; o > 0; o >>= 1) v += __shfl_xor_sync(0xffffffffu, v, o);
    return v;
}
__device__ __forceinline__ uint32_t smem_to_u32(const void* p) {
    uint32_t a;
    asm("{ .reg .u64 t; cvta.to.shared.u64 t, %1; cvt.u32.u64 %0, t; }" : "=r"(a) : "l"(p));
    return a;
}
__device__ __forceinline__ uint32_t swz(uint32_t x) { return x ^ ((x >> 3) & 0x70); }

__device__ __forceinline__ void ldsm_x4(uint32_t* r, uint32_t addr) {
    asm volatile("ldmatrix.sync.aligned.m8n8.x4.shared.b16 {%0,%1,%2,%3}, [%4];"
                 : "=r"(r[0]), "=r"(r[1]), "=r"(r[2]), "=r"(r[3]) : "r"(addr));
}
__device__ __forceinline__ void ldsm_x2(uint32_t* r, uint32_t addr) {
    asm volatile("ldmatrix.sync.aligned.m8n8.x2.shared.b16 {%0,%1}, [%2];"
                 : "=r"(r[0]), "=r"(r[1]) : "r"(addr));
}
__device__ __forceinline__ void mma_bf16(float* c, const uint32_t* a, const uint32_t* b) {
    asm volatile("mma.sync.aligned.m16n8k16.row.col.f32.bf16.bf16.f32 "
                 "{%0,%1,%2,%3}, {%4,%5,%6,%7}, {%8,%9}, {%0,%1,%2,%3};"
                 : "+f"(c[0]), "+f"(c[1]), "+f"(c[2]), "+f"(c[3])
                 : "r"(a[0]), "r"(a[1]), "r"(a[2]), "r"(a[3]), "r"(b[0]), "r"(b[1]));
}
__device__ __forceinline__ void split_bf16(float v, __nv_bfloat16& h, __nv_bfloat16& l) {
    h = __float2bfloat16(v);
    l = __float2bfloat16(v - __bfloat162float(h));
}
__device__ __forceinline__ void cp_async16(uint32_t dst, const void* src) {
    asm volatile("cp.async.ca.shared.global [%0], [%1], 16;" :: "r"(dst), "l"(src));
}
__device__ __forceinline__ void cp16z(uint32_t dst, const void* src, int sz) {
    asm volatile("cp.async.ca.shared.global [%0], [%1], 16, %2;"
                 :: "r"(dst), "l"(src), "r"(sz));
}
__device__ __forceinline__ void cp_commit() {
    asm volatile("cp.async.commit_group;" ::: "memory");
}
template<int N> __device__ __forceinline__ void cp_wait() {
    asm volatile("cp.async.wait_group %0;" :: "n"(N) : "memory");
}

// ============ HMMA split-bf16 GEMM (double-buffered cp.async) ============
// C[M x 256] = A[M x 256] @ W^T;  A bf16 hi/lo, W bf16 hi/lo [256 n][256 k].
// emode 0: C = acc + bias
// emode 2: nodes += leaky_relu(acc+bias), masked by data; y hi/lo emitted pre-mask
// blockIdx.z==1 -> second problem (wh1/wl1/b1/C1).
__global__ void __launch_bounds__(256, 1)
gemm_mma_kernel(const __nv_bfloat16* __restrict__ Ahi, const __nv_bfloat16* __restrict__ Alo,
                const __nv_bfloat16* __restrict__ wh0, const __nv_bfloat16* __restrict__ wl0,
                const float* __restrict__ b0, float* __restrict__ C0,
                const __nv_bfloat16* __restrict__ wh1, const __nv_bfloat16* __restrict__ wl1,
                const float* __restrict__ b1, float* __restrict__ C1,
                int M, int emode, const int* __restrict__ data,
                __nv_bfloat16* __restrict__ yhi, __nv_bfloat16* __restrict__ ylo)
{
    extern __shared__ char smem[];
    const __nv_bfloat16* wh = wh0; const __nv_bfloat16* wl = wl0;
    const float* bias = b0; float* C = C0;
    if (blockIdx.z == 1) { wh = wh1; wl = wl1; bias = b1; C = C1; }

    const uint32_t sb = smem_to_u32(smem);
    const uint32_t STG = 65536;  // per-stage: A_HI 0 | A_LO 16384 | B_HI 32768 | B_LO 49152
    const int tid = threadIdx.x, lane = tid & 31, wid = tid >> 5;
    const int warpM = wid & 1, warpN = wid >> 1;
    const int m0 = blockIdx.y * 128, n0 = blockIdx.x * 128;
    const int half = tid >> 7, r = tid & 127;

    float c[4][4][4];
#pragma unroll
    for (int i = 0; i < 4; i++)
#pragma unroll
        for (int j = 0; j < 4; j++)
#pragma unroll
            for (int l = 0; l < 4; l++) c[i][j][l] = 0.f;

    auto do_stage = [&](int kc) {
        const int k0 = kc << 6;
        const uint32_t bufo = (uint32_t)(kc & 1) * STG;
        {
            int grow = m0 + r;
            const __nv_bfloat16* srcp = (half ? Alo : Ahi) + (size_t)grow * HH + k0;
            int sz = (grow < M) ? 16 : 0;
            uint32_t dbase = sb + bufo + (uint32_t)half * 16384u;
            uint32_t rb = (uint32_t)r * 128u;
#pragma unroll
            for (int i = 0; i < 8; i++)
                cp16z(dbase + swz(rb + i * 16u), srcp + i * 8, sz);
        }
        {
            const __nv_bfloat16* srcp = (half ? wl : wh) + (size_t)(n0 + r) * HH + k0;
            uint32_t dbase = sb + bufo + 32768u + (uint32_t)half * 16384u;
            uint32_t rb = (uint32_t)r * 128u;
#pragma unroll
            for (int i = 0; i < 8; i++)
                cp_async16(dbase + swz(rb + i * 16u), srcp + i * 8);
        }
        cp_commit();
    };

    do_stage(0);
    do_stage(1);

    for (int kc = 0; kc < 4; kc++) {
        if (kc < 3) cp_wait<1>(); else cp_wait<0>();
        __syncthreads();
        const uint32_t bufo = (uint32_t)(kc & 1) * STG;
#pragma unroll
        for (int ks = 0; ks < 4; ks++) {
            uint32_t ah[4][4], al[4][4];
#pragma unroll
            for (int mt = 0; mt < 4; mt++) {
                int row = warpM * 64 + mt * 16 + (lane & 15);
                uint32_t off = swz((uint32_t)row * 128u + ks * 32u + ((lane >> 4) << 4));
                ldsm_x4(ah[mt], sb + bufo + off);
                ldsm_x4(al[mt], sb + bufo + 16384u + off);
            }
            uint32_t bh[4][2], bl[4][2];
#pragma unroll
            for (int nt = 0; nt < 4; nt++) {
                int n = warpN * 32 + nt * 8 + (lane & 7);
                uint32_t off = swz((uint32_t)n * 128u + ks * 32u + (((lane >> 3) & 1) << 4));
                ldsm_x2(bh[nt], sb + bufo + 32768u + off);
                ldsm_x2(bl[nt], sb + bufo + 49152u + off);
            }
#pragma unroll
            for (int mt = 0; mt < 4; mt++)
#pragma unroll
                for (int nt = 0; nt < 4; nt++) {
                    mma_bf16(c[mt][nt], ah[mt], bh[nt]);
                    mma_bf16(c[mt][nt], ah[mt], bl[nt]);
                    mma_bf16(c[mt][nt], al[mt], bh[nt]);
                }
        }
        __syncthreads();
        if (kc + 2 < 4) do_stage(kc + 2);
    }

    // ---- epilogue ----
    const int gid = lane >> 2, tig = lane & 3;
#pragma unroll
    for (int mt = 0; mt < 4; mt++)
#pragma unroll
        for (int nt = 0; nt < 4; nt++) {
            int col = n0 + warpN * 32 + nt * 8 + tig * 2;
            float bc0 = bias[col], bc1 = bias[col + 1];
#pragma unroll
            for (int h = 0; h < 2; h++) {
                int row = m0 + warpM * 64 + mt * 16 + gid + h * 8;
                if (row >= M) continue;
                float v0 = c[mt][nt][h * 2 + 0] + bc0;
                float v1 = c[mt][nt][h * 2 + 1] + bc1;
                float* crow = C + (size_t)row * HH + col;
                if (emode == 2) {
                    float l0 = v0 > 0.f ? v0 : 0.01f * v0;
                    float l1 = v1 > 0.f ? v1 : 0.01f * v1;
                    float n0v = crow[0] + l0;
                    float n1v = crow[1] + l1;
                    bool z = (data[row] == 1);
                    *(float2*)crow = z ? make_float2(0.f, 0.f) : make_float2(n0v, n1v);
                    int b = row >> 9, ll = row & (LL - 1);
                    size_t yo = (size_t)(b * LY + 1 + ll) * HH + col;
                    __nv_bfloat16 h0, l0b, h1, l1b;
                    split_bf16(n0v, h0, l0b);
                    split_bf16(n1v, h1, l1b);
                    *(__nv_bfloat162*)(yhi + yo) = __nv_bfloat162(h0, h1);
                    *(__nv_bfloat162*)(ylo + yo) = __nv_bfloat162(l0b, l1b);
                } else {
                    *(float2*)crow = make_float2(v0, v1);
                }
            }
        }
}

// ============ embedding HMMA GEMM: x0 = split(emb[data]) @ embW^T + b + pos ============
__global__ void __launch_bounds__(256, 1)
gemm_emb_mma_kernel(const int* __restrict__ data, const float* __restrict__ emb,
                    const __nv_bfloat16* __restrict__ whE, const __nv_bfloat16* __restrict__ wlE,
                    const float* __restrict__ bias, const float* __restrict__ pos,
                    float* __restrict__ C)
{
    extern __shared__ char smem[];
    const uint32_t sb = smem_to_u32(smem);
    const int tid = threadIdx.x, lane = tid & 31, wid = tid >> 5;
    const int warpM = wid & 1, warpN = wid >> 1;
    const int m0 = blockIdx.y * 128, n0 = blockIdx.x * 128;
    const int half = tid >> 7, r = tid & 127;

    float c[4][4][4];
#pragma unroll
    for (int i = 0; i < 4; i++)
#pragma unroll
        for (int j = 0; j < 4; j++)
#pragma unroll
            for (int l = 0; l < 4; l++) c[i][j][l] = 0.f;

    for (int kc = 0; kc < 5; kc++) {
        const int k0 = kc << 6;
        // ---- A stage: gather fp32, split, write bf16 (this half's component) ----
        {
            int grow = m0 + r;
            const float* srow = emb + (size_t)data[grow] * E_DIM;
            char* dbase = smem + half * 16384;
            uint32_t rb = (uint32_t)r * 128u;
#pragma unroll
            for (int i = 0; i < 8; i++) {
                union { uint4 u; unsigned short s[8]; } pk;
#pragma unroll
                for (int j = 0; j < 8; j++) {
                    int kk = k0 + i * 8 + j;
                    float f = (kk < E_DIM) ? srow[kk] : 0.f;
                    __nv_bfloat16 h, l;
                    split_bf16(f, h, l);
                    pk.s[j] = __bfloat16_as_ushort(half ? l : h);
                }
                *(uint4*)(dbase + swz(rb + i * 16u)) = pk.u;
            }
        }
        // ---- B stage ----
        {
            const __nv_bfloat16* srcp = (half ? wlE : whE) + (size_t)(n0 + r) * 320 + k0;
            char* dbase = smem + 32768 + half * 16384;
            uint32_t rb = (uint32_t)r * 128u;
#pragma unroll
            for (int i = 0; i < 8; i++)
                *(uint4*)(dbase + swz(rb + i * 16u)) = *(const uint4*)(srcp + i * 8);
        }
        __syncthreads();
#pragma unroll
        for (int ks = 0; ks < 4; ks++) {
            uint32_t ah[4][4], al[4][4];
#pragma unroll
            for (int mt = 0; mt < 4; mt++) {
                int row = warpM * 64 + mt * 16 + (lane & 15);
                uint32_t off = swz((uint32_t)row * 128u + ks * 32u + ((lane >> 4) << 4));
                ldsm_x4(ah[mt], sb + off);
                ldsm_x4(al[mt], sb + 16384u + off);
            }
            uint32_t bh[4][2], bl[4][2];
#pragma unroll
            for (int nt = 0; nt < 4; nt++) {
                int n = warpN * 32 + nt * 8 + (lane & 7);
                uint32_t off = swz((uint32_t)n * 128u + ks * 32u + (((lane >> 3) & 1) << 4));
                ldsm_x2(bh[nt], sb + 32768u + off);
                ldsm_x2(bl[nt], sb + 49152u + off);
            }
#pragma unroll
            for (int mt = 0; mt < 4; mt++)
#pragma unroll
                for (int nt = 0; nt < 4; nt++) {
                    mma_bf16(c[mt][nt], ah[mt], bh[nt]);
                    mma_bf16(c[mt][nt], ah[mt], bl[nt]);
                    mma_bf16(c[mt][nt], al[mt], bh[nt]);
                }
        }
        __syncthreads();
    }

    const int gid = lane >> 2, tig = lane & 3;
#pragma unroll
    for (int mt = 0; mt < 4; mt++)
#pragma unroll
        for (int nt = 0; nt < 4; nt++) {
            int col = n0 + warpN * 32 + nt * 8 + tig * 2;
            float bc0 = bias[col], bc1 = bias[col + 1];
#pragma unroll
            for (int h = 0; h < 2; h++) {
                int row = m0 + warpM * 64 + mt * 16 + gid + h * 8;
                int pr = (row & (LL - 1)) * HH + col;
                float v0 = c[mt][nt][h * 2 + 0] + bc0 + pos[pr];
                float v1 = c[mt][nt][h * 2 + 1] + bc1 + pos[pr + 1];
                *(float2*)&C[(size_t)row * HH + col] = make_float2(v0, v1);
            }
        }
}

// ============ weight prep: coalesced tiled transpose + split ============
// grid (8, 10, 31), block (32, 8). slots 0..29: [256][256]; slot 30: emb_fc_W [300][256]->[256][320]
__global__ void prep_w_kernel(const float* __restrict__ rWQ, const float* __restrict__ rWK,
                              const float* __restrict__ rWO, const float* __restrict__ sWK,
                              const float* __restrict__ sWV, const float* __restrict__ embW,
                              __nv_bfloat16* __restrict__ whi, __nv_bfloat16* __restrict__ wlo,
                              __nv_bfloat16* __restrict__ whiE, __nv_bfloat16* __restrict__ wloE)
{
    int slot = blockIdx.z;
    int n0 = blockIdx.x * 32, k0 = blockIdx.y * 32;
    const float* W; int K, Kpad;
    __nv_bfloat16 *oh, *ol;
    if (slot < 30) {
        if (k0 >= 256) return;
        int fam = slot / 6, it = slot % 6;
        W = (fam == 0 ? rWQ : fam == 1 ? rWK : fam == 2 ? rWO :
             fam == 3 ? sWK : sWV) + (size_t)it * HH * HH;
        K = 256; Kpad = 256;
        oh = whi + (size_t)slot * 65536; ol = wlo + (size_t)slot * 65536;
    } else {
        W = embW; K = E_DIM; Kpad = 320; oh = whiE; ol = wloE;
    }
    __shared__ float tile[32][33];
    int tx = threadIdx.x, ty = threadIdx.y;
#pragma unroll
    for (int i = 0; i < 4; i++) {
        int k = k0 + ty + i * 8;
        tile[ty + i * 8][tx] = (k < K) ? W[(size_t)k * HH + n0 + tx] : 0.f;
    }
    __syncthreads();
#pragma unroll
    for (int i = 0; i < 4; i++) {
        int n = n0 + ty + i * 8;
        float x = tile[tx][ty + i * 8];
        __nv_bfloat16 h, l;
        split_bf16(x, h, l);
        size_t o = (size_t)n * Kpad + k0 + tx;
        oh[o] = h; ol[o] = l;
    }
}

// ---------------- layernorm: one warp per row -> split bf16 out ----------------
__global__ void __launch_bounds__(256)
layernorm_kernel(const float* __restrict__ x,
                 __nv_bfloat16* __restrict__ yh, __nv_bfloat16* __restrict__ yl,
                 const float* __restrict__ g, const float* __restrict__ b)
{
    int w = threadIdx.x >> 5, lane = threadIdx.x & 31;
    int row = blockIdx.x * 8 + w;
    const float* xr = x + (size_t)row * HH;
    float4 v0 = *(const float4*)&xr[lane * 4];
    float4 v1 = *(const float4*)&xr[lane * 4 + 128];
    float s = v0.x + v0.y + v0.z + v0.w + v1.x + v1.y + v1.z + v1.w;
    float mean = warpReduceSum(s) * (1.f / HH);
    float d[8] = { v0.x - mean, v0.y - mean, v0.z - mean, v0.w - mean,
                   v1.x - mean, v1.y - mean, v1.z - mean, v1.w - mean };
    float s2 = 0.f;
#pragma unroll
    for (int i = 0; i < 8; i++) s2 += d[i] * d[i];
    float var = warpReduceSum(s2) * (1.f / HH);
    float rs = rsqrtf(var + 1e-5f);
    float4 g0 = *(const float4*)&g[lane * 4];
    float4 g1 = *(const float4*)&g[lane * 4 + 128];
    float4 bb0 = *(const float4*)&b[lane * 4];
    float4 bb1 = *(const float4*)&b[lane * 4 + 128];
    float o[8] = { g0.x*d[0]*rs + bb0.x, g0.y*d[1]*rs + bb0.y,
                   g0.z*d[2]*rs + bb0.z, g0.w*d[3]*rs + bb0.w,
                   g1.x*d[4]*rs + bb1.x, g1.y*d[5]*rs + bb1.y,
                   g1.z*d[6]*rs + bb1.z, g1.w*d[7]*rs + bb1.w };
#pragma unroll
    for (int seg = 0; seg < 2; seg++) {
        ushort4 hv, lv;
        __nv_bfloat16 h, l;
        split_bf16(o[seg*4+0], h, l); hv.x = __bfloat16_as_ushort(h); lv.x = __bfloat16_as_ushort(l);
        split_bf16(o[seg*4+1], h, l); hv.y = __bfloat16_as_ushort(h); lv.y = __bfloat16_as_ushort(l);
        split_bf16(o[seg*4+2], h, l); hv.z = __bfloat16_as_ushort(h); lv.z = __bfloat16_as_ushort(l);
        split_bf16(o[seg*4+3], h, l); hv.w = __bfloat16_as_ushort(h); lv.w = __bfloat16_as_ushort(l);
        size_t off = (size_t)row * HH + lane * 4 + seg * 128;
        *(ushort4*)(yh + off) = hv;
        *(ushort4*)(yl + off) = lv;
    }
}

// ---------------- relay = mean over L (64x4 layout) ----------------
__global__ void __launch_bounds__(256)
relay_mean_kernel(const float* __restrict__ x0, float* __restrict__ relay)
{
    int b = blockIdx.x;
    int tx = threadIdx.x & 63, ty = threadIdx.x >> 6;
    float4 acc = make_float4(0.f, 0.f, 0.f, 0.f);
    for (int l = ty; l < LL; l += 4) {
        float4 v = *(const float4*)&x0[(size_t)(b * LL + l) * HH + tx * 4];
        acc.x += v.x; acc.y += v.y; acc.z += v.z; acc.w += v.w;
    }
    __shared__ float4 part[4][64];
    part[ty][tx] = acc;
    __syncthreads();
    if (ty == 0) {
        float4 s = part[0][tx];
#pragma unroll
        for (int i = 1; i < 4; i++) {
            s.x += part[i][tx].x; s.y += part[i][tx].y;
            s.z += part[i][tx].z; s.w += part[i][tx].w;
        }
        const float inv = 1.f / LL;
        *(float4*)&relay[b * HH + tx * 4] =
            make_float4(s.x * inv, s.y * inv, s.z * inv, s.w * inv);
    }
}

// ---------------- fused relay projections: ak, av, q2, y-row ----------------
__global__ void __launch_bounds__(256)
rowproj4_kernel(const float* __restrict__ relay,
                const float* __restrict__ WK, const float* __restrict__ bK, float* __restrict__ ak,
                const float* __restrict__ WV, const float* __restrict__ bV, float* __restrict__ av,
                const float* __restrict__ sWQ, const float* __restrict__ sbQ, float* __restrict__ q2,
                __nv_bfloat16* __restrict__ yh, __nv_bfloat16* __restrict__ yl)
{
    int seg = blockIdx.x >> 5, b = blockIdx.x & 31, t = threadIdx.x;
    if (seg == 3) {
        __nv_bfloat16 h, l;
        split_bf16(relay[b * HH + t], h, l);
        size_t o = (size_t)(b * LY) * HH + t;
        yh[o] = h; yl[o] = l;
        return;
    }
    const float* W  = seg == 0 ? WK : seg == 1 ? WV : sWQ;
    const float* bi = seg == 0 ? bK : seg == 1 ? bV : sbQ;
    float* o        = seg == 0 ? ak : seg == 1 ? av : q2;
    __shared__ float xin[HH];
    xin[t] = relay[b * HH + t];
    __syncthreads();
    float s = bi[t];
#pragma unroll 8
    for (int k = 0; k < HH; k++) s += xin[k] * W[k * HH + t];
    o[b * HH + t] = s;
}

__global__ void rowproj_kernel(const float* __restrict__ in, const float* __restrict__ W,
                               const float* __restrict__ bias, float* __restrict__ out,
                               int lrelu)
{
    __shared__ float xin[HH];
    int b = blockIdx.x, t = threadIdx.x;
    xin[t] = in[b * HH + t];
    __syncthreads();
    float s = bias[t];
#pragma unroll 8
    for (int k = 0; k < HH; k++) s += xin[k] * W[k * HH + t];
    if (lrelu) s = s > 0.f ? s : 0.01f * s;
    out[b * HH + t] = s;
}

// ---------------- msa1 windowed attention -> split bf16 att ----------------
__global__ void __launch_bounds__(256)
msa1_attn_kernel(const float* __restrict__ q, const float* __restrict__ k,
                 const float* __restrict__ ak, const float* __restrict__ av,
                 __nv_bfloat16* __restrict__ atth, __nv_bfloat16* __restrict__ attl)
{
    int row = blockIdx.x;
    int b = row >> 9, l = row & (LL - 1);
    int t = threadIdx.x;
    int c = t;
    float qv  = q[(size_t)row * HH + c];
    float k0v = k[(size_t)row * HH + c];
    float kmv = (l > 0)      ? k[(size_t)(row - 1) * HH + c] : 0.f;
    float kpv = (l < LL - 1) ? k[(size_t)(row + 1) * HH + c] : 0.f;
    float akv = ak[b * HH + c];
    float avv = av[b * HH + c];
    const float sc = 0.17677669529663687f;
    float s0 = warpReduceSum(qv * akv) * sc;
    float s1 = warpReduceSum(qv * kmv) * sc;
    float s2 = warpReduceSum(qv * k0v) * sc;
    float s3 = warpReduceSum(qv * kpv) * sc;
    float m = fmaxf(fmaxf(s0, s1), fmaxf(s2, s3));
    float e0 = expf(s0 - m), e1 = expf(s1 - m), e2 = expf(s2 - m), e3 = expf(s3 - m);
    float inv = 1.f / (e0 + e1 + e2 + e3);
    float o = (e0 * avv + e1 * kmv + e2 * k0v + e3 * kpv) * inv;
    __nv_bfloat16 h, lo;
    split_bf16(o, h, lo);
    atth[(size_t)row * HH + c] = h;
    attl[(size_t)row * HH + c] = lo;
}

// ---------------- msa2 ----------------
__global__ void __launch_bounds__(256)
msa2_attn_kernel(const float* __restrict__ q2, const float* __restrict__ yk,
                 const float* __restrict__ yv, float* __restrict__ att2)
{
    __shared__ float sc[LY];
    __shared__ float red[8];
    __shared__ float part[8][HD];
    int b = blockIdx.x >> 3, h = blockIdx.x & 7;
    int t = threadIdx.x, w = t >> 5, d = t & 31;
    const float scale = 0.17677669529663687f;
    float qv = q2[b * HH + h * HD + d];
    const float* kb = yk + (size_t)b * LY * HH + h * HD;
    const float* vb = yv + (size_t)b * LY * HH + h * HD;
    for (int l = w; l < LY; l += 8) {
        float s = warpReduceSum(qv * kb[(size_t)l * HH + d]) * scale;
        if (d == 0) sc[l] = s;
    }
    __syncthreads();
    float m = -3.4e38f;
    for (int l = t; l < LY; l += 256) m = fmaxf(m, sc[l]);
#pragma unroll
    for (int o = 16; o > 0; o >>= 1) m = fmaxf(m, __shfl_xor_sync(0xffffffffu, m, o));
    if (d == 0) red[w] = m;
    __syncthreads();
    float mm = red[0];
#pragma unroll
    for (int i = 1; i < 8; i++) mm = fmaxf(mm, red[i]);
    __syncthreads();
    float ssum = 0.f;
    for (int l = t; l < LY; l += 256) { float e = expf(sc[l] - mm); sc[l] = e; ssum += e; }
    ssum = warpReduceSum(ssum);
    if (d == 0) red[w] = ssum;
    __syncthreads();
    float tot = 0.f;
#pragma unroll
    for (int i = 0; i < 8; i++) tot += red[i];
    float acc = 0.f;
    for (int l = w; l < LY; l += 8) acc += sc[l] * vb[(size_t)l * HH + d];
    part[w][d] = acc;
    __syncthreads();
    if (w == 0) {
        float o = 0.f;
#pragma unroll
        for (int i = 0; i < 8; i++) o += part[i][d];
        att2[b * HH + h * HD + d] = o / tot;
    }
}

// ---------------- final: 0.5*max_l(nodes) + 0.5*relay ----------------
__global__ void __launch_bounds__(256)
final_kernel(const float* __restrict__ nodes, const float* __restrict__ relay,
             float* __restrict__ out)
{
    int b = blockIdx.x;
    int tx = threadIdx.x & 63, ty = threadIdx.x >> 6;
    float4 m = make_float4(-3.4e38f, -3.4e38f, -3.4e38f, -3.4e38f);
    for (int l = ty; l < LL; l += 4) {
        float4 v = *(const float4*)&nodes[(size_t)(b * LL + l) * HH + tx * 4];
        m.x = fmaxf(m.x, v.x); m.y = fmaxf(m.y, v.y);
        m.z = fmaxf(m.z, v.z); m.w = fmaxf(m.w, v.w);
    }
    __shared__ float4 part[4][64];
    part[ty][tx] = m;
    __syncthreads();
    if (ty == 0) {
        float4 s = part[0][tx];
#pragma unroll
        for (int i = 1; i < 4; i++) {
            s.x = fmaxf(s.x, part[i][tx].x); s.y = fmaxf(s.y, part[i][tx].y);
            s.z = fmaxf(s.z, part[i][tx].z); s.w = fmaxf(s.w, part[i][tx].w);
        }
        float4 r = *(const float4*)&relay[b * HH + tx * 4];
        *(float4*)&out[b * HH + tx * 4] =
            make_float4(0.5f * s.x + 0.5f * r.x, 0.5f * s.y + 0.5f * r.y,
                        0.5f * s.z + 0.5f * r.z, 0.5f * s.w + 0.5f * r.w);
    }
}

// ---------------- host ----------------
extern "C" void kernel_launch(void* const* d_in, const int* in_sizes, int n_in,
                              void* d_out, int out_size)
{
    const int*   data     = (const int*)  d_in[0];
    const float* emb      = (const float*)d_in[1];
    const float* emb_fc_W = (const float*)d_in[2];
    const float* emb_fc_b = (const float*)d_in[3];
    const float* pos_emb  = (const float*)d_in[4];
    const float* ln_g     = (const float*)d_in[5];
    const float* ln_b     = (const float*)d_in[6];
    const float* r_WQ = (const float*)d_in[7];
    const float* r_bQ = (const float*)d_in[8];
    const float* r_WK = (const float*)d_in[9];
    const float* r_bK = (const float*)d_in[10];
    const float* r_WV = (const float*)d_in[11];
    const float* r_bV = (const float*)d_in[12];
    const float* r_WO = (const float*)d_in[13];
    const float* r_bO = (const float*)d_in[14];
    const float* s_WQ = (const float*)d_in[15];
    const float* s_bQ = (const float*)d_in[16];
    const float* s_WK = (const float*)d_in[17];
    const float* s_bK = (const float*)d_in[18];
    const float* s_WV = (const float*)d_in[19];
    const float* s_bV = (const float*)d_in[20];
    const float* s_WO = (const float*)d_in[21];
    const float* s_bO = (const float*)d_in[22];
    float* out = (float*)d_out;
    (void)in_sizes; (void)n_in; (void)out_size;

    float *nodes, *q, *k, *yk, *yv, *relay, *ak, *av, *q2, *att2;
    __nv_bfloat16 *whi, *wlo, *whiE, *wloE, *nlnh, *nlnl, *atth, *attl, *yh, *yl;
    cudaGetSymbolAddress((void**)&nodes, g_nodes);
    cudaGetSymbolAddress((void**)&q,     g_q);
    cudaGetSymbolAddress((void**)&k,     g_k);
    cudaGetSymbolAddress((void**)&yk,    g_yk);
    cudaGetSymbolAddress((void**)&yv,    g_yv);
    cudaGetSymbolAddress((void**)&relay, g_relay);
    cudaGetSymbolAddress((void**)&ak,    g_ak);
    cudaGetSymbolAddress((void**)&av,    g_av);
    cudaGetSymbolAddress((void**)&q2,    g_q2);
    cudaGetSymbolAddress((void**)&att2,  g_att2);
    cudaGetSymbolAddress((void**)&whi,   g_whi);
    cudaGetSymbolAddress((void**)&wlo,   g_wlo);
    cudaGetSymbolAddress((void**)&whiE,  g_whiE);
    cudaGetSymbolAddress((void**)&wloE,  g_wloE);
    cudaGetSymbolAddress((void**)&nlnh,  g_nlnh);
    cudaGetSymbolAddress((void**)&nlnl,  g_nlnl);
    cudaGetSymbolAddress((void**)&atth,  g_atth);
    cudaGetSymbolAddress((void**)&attl,  g_attl);
    cudaGetSymbolAddress((void**)&yh,    g_yh);
    cudaGetSymbolAddress((void**)&yl,    g_yl);

    const int M1 = BB * LL;    // 16384
    const int M2 = BB * LY;    // 16416
    const int MMA_SMEM  = 131072;  // 2-stage double buffer
    const int EMB_SMEM  = 65536;
    static int attr_done = 0;
    if (!attr_done) {
        cudaFuncSetAttribute(gemm_mma_kernel,
                             cudaFuncAttributeMaxDynamicSharedMemorySize, MMA_SMEM);
        cudaFuncSetAttribute(gemm_emb_mma_kernel,
                             cudaFuncAttributeMaxDynamicSharedMemorySize, EMB_SMEM);
        attr_done = 1;
    }

    dim3 blk(256);
    auto WH = [&](int slot) { return whi + (size_t)slot * 65536; };
    auto WL = [&](int slot) { return wlo + (size_t)slot * 65536; };

    // prep split-transposed weights (slots: Q=0..5, K=6..11, O=12..17, sK=18..23, sV=24..29, emb=30)
    prep_w_kernel<<<dim3(8, 10, 31), dim3(32, 8)>>>(r_WQ, r_WK, r_WO, s_WK, s_WV, emb_fc_W,
                                                    whi, wlo, whiE, wloE);

    // x0 = emb[data] @ emb_fc_W + b + pos ; relay = mean_L(x0)
    gemm_emb_mma_kernel<<<dim3(2, 128), blk, EMB_SMEM>>>(data, emb, whiE, wloE,
                                                         emb_fc_b, pos_emb, nodes);
    relay_mean_kernel<<<BB, blk>>>(nodes, relay);

    for (int i = 0; i < ITERS; i++) {
        const float* bQ = r_bQ + i * HH;
        const float* bK = r_bK + i * HH;
        const float* WK = r_WK + i * HH * HH;
        const float* WV = r_WV + i * HH * HH;
        const float* bV = r_bV + i * HH;
        const float* bO = r_bO + i * HH;
        const float* sWQ = s_WQ + i * HH * HH; const float* sbQ = s_bQ + i * HH;
        const float* sbK = s_bK + i * HH;
        const float* sbV = s_bV + i * HH;
        const float* sWO = s_WO + i * HH * HH; const float* sbO = s_bO + i * HH;

        layernorm_kernel<<<M1 / 8, blk>>>(nodes, nlnh, nlnl, ln_g + i * HH, ln_b + i * HH);
        // fused Q + K projections (HMMA, double-buffered)
        gemm_mma_kernel<<<dim3(2, 128, 2), blk, MMA_SMEM>>>(
            nlnh, nlnl, WH(i), WL(i), bQ, q, WH(6 + i), WL(6 + i), bK, k,
            M1, 0, nullptr, nullptr, nullptr);
        // fused ak + av + q2 + relay->y row
        rowproj4_kernel<<<4 * BB, blk>>>(relay, WK, bK, ak, WV, bV, av,
                                         sWQ, sbQ, q2, yh, yl);
        msa1_attn_kernel<<<M1, blk>>>(q, k, ak, av, atth, attl);
        // O projection + leaky residual + mask + y emit (HMMA)
        gemm_mma_kernel<<<dim3(2, 128, 1), blk, MMA_SMEM>>>(
            atth, attl, WH(12 + i), WL(12 + i), bO, nodes,
            nullptr, nullptr, nullptr, nullptr,
            M1, 2, data, yh, yl);
        // fused yK + yV (HMMA)
        gemm_mma_kernel<<<dim3(2, 129, 2), blk, MMA_SMEM>>>(
            yh, yl, WH(18 + i), WL(18 + i), sbK, yk,
            WH(24 + i), WL(24 + i), sbV, yv,
            M2, 0, nullptr, nullptr, nullptr);
        msa2_attn_kernel<<<BB * NH, blk>>>(q2, yk, yv, att2);
        rowproj_kernel<<<BB, HH>>>(att2, sWO, sbO, relay, 1);
    }
    final_kernel<<<BB, blk>>>(nodes, relay, out);
}

// round 10
// speedup vs baseline: 3.1805x; 1.3668x over previous
#include <cuda_runtime.h>
#include <cuda_fp16.h>
#include <math.h>
#include <cstdint>

#define BB   32
#define LL   512
#define HH   256
#define NH   8
#define HD   32
#define ITERS 6
#define E_DIM 300
#define LY   513  /* 1 + L */

typedef unsigned long long ull;

// ---------------- scratch (device globals; no allocation) ----------------
__device__ float g_nodes[BB*LL*HH];
__device__ float g_q    [BB*LL*HH];
__device__ float g_k    [BB*LL*HH];
__device__ float g_yk   [BB*LY*HH];
__device__ float g_yv   [BB*LY*HH];
__device__ float g_relay[BB*HH];
__device__ float g_ak   [BB*HH];
__device__ float g_av   [BB*HH];
__device__ float g_q2   [BB*HH];
__device__ float g_att2 [BB*HH];
// fp16 activations (single precision-split NOT needed on A side for 2-pass)
__device__ __align__(16) __half g_nln16[BB*LL*HH];
__device__ __align__(16) __half g_att16[BB*LL*HH];
__device__ __align__(16) __half g_y16  [BB*LY*HH];
// split-fp16 transposed weights: 30 slots of [256 n][256 k]
__device__ __align__(16) __half g_w16h[30*65536];
__device__ __align__(16) __half g_w16l[30*65536];
// emb_fc split-transposed: [256 n][320 k] (zero-padded k>=300)
__device__ __align__(16) __half g_wEh[256*320];
__device__ __align__(16) __half g_wEl[256*320];

// ---------------- helpers ----------------
__device__ __forceinline__ float warpReduceSum(float v) {
#pragma unroll
    for (int o = 16; o > 0; o >>= 1) v += __shfl_xor_sync(0xffffffffu, v, o);
    return v;
}
__device__ __forceinline__ uint32_t smem_to_u32(const void* p) {
    uint32_t a;
    asm("{ .reg .u64 t; cvta.to.shared.u64 t, %1; cvt.u32.u64 %0, t; }" : "=r"(a) : "l"(p));
    return a;
}
__device__ __forceinline__ uint32_t swz(uint32_t x) { return x ^ ((x >> 3) & 0x70); }

__device__ __forceinline__ void ldsm_x4(uint32_t* r, uint32_t addr) {
    asm volatile("ldmatrix.sync.aligned.m8n8.x4.shared.b16 {%0,%1,%2,%3}, [%4];"
                 : "=r"(r[0]), "=r"(r[1]), "=r"(r[2]), "=r"(r[3]) : "r"(addr));
}
__device__ __forceinline__ void ldsm_x2(uint32_t* r, uint32_t addr) {
    asm volatile("ldmatrix.sync.aligned.m8n8.x2.shared.b16 {%0,%1}, [%2];"
                 : "=r"(r[0]), "=r"(r[1]) : "r"(addr));
}
__device__ __forceinline__ void mma_fp16(float* c, const uint32_t* a, const uint32_t* b) {
    asm volatile("mma.sync.aligned.m16n8k16.row.col.f32.f16.f16.f32 "
                 "{%0,%1,%2,%3}, {%4,%5,%6,%7}, {%8,%9}, {%0,%1,%2,%3};"
                 : "+f"(c[0]), "+f"(c[1]), "+f"(c[2]), "+f"(c[3])
                 : "r"(a[0]), "r"(a[1]), "r"(a[2]), "r"(a[3]), "r"(b[0]), "r"(b[1]));
}
__device__ __forceinline__ void split_fp16(float v, __half& h, __half& l) {
    h = __float2half_rn(v);
    l = __float2half_rn(v - __half2float(h));
}
__device__ __forceinline__ void cp_async16(uint32_t dst, const void* src) {
    asm volatile("cp.async.ca.shared.global [%0], [%1], 16;" :: "r"(dst), "l"(src));
}
__device__ __forceinline__ void cp16z(uint32_t dst, const void* src, int sz) {
    asm volatile("cp.async.ca.shared.global [%0], [%1], 16, %2;"
                 :: "r"(dst), "l"(src), "r"(sz));
}
__device__ __forceinline__ void cp_commit() {
    asm volatile("cp.async.commit_group;" ::: "memory");
}
template<int N> __device__ __forceinline__ void cp_wait() {
    asm volatile("cp.async.wait_group %0;" :: "n"(N) : "memory");
}

// ============ HMMA fp16 2-pass GEMM (double-buffered cp.async, 2 blocks/SM) ============
// C[M x 256] = A[M x 256] @ (Wh + Wl)^T;  A fp16, W split fp16 [256 n][256 k].
// emode 0: C = acc + bias
// emode 2: nodes += leaky_relu(acc+bias), masked by data; y fp16 emitted pre-mask
// blockIdx.z==1 -> second problem (wh1/wl1/b1/C1).
__global__ void __launch_bounds__(256, 2)
gemm_mma_kernel(const __half* __restrict__ A16,
                const __half* __restrict__ wh0, const __half* __restrict__ wl0,
                const float* __restrict__ b0, float* __restrict__ C0,
                const __half* __restrict__ wh1, const __half* __restrict__ wl1,
                const float* __restrict__ b1, float* __restrict__ C1,
                int M, int emode, const int* __restrict__ data,
                __half* __restrict__ y16)
{
    extern __shared__ char smem[];
    const __half* wh = wh0; const __half* wl = wl0;
    const float* bias = b0; float* C = C0;
    if (blockIdx.z == 1) { wh = wh1; wl = wl1; bias = b1; C = C1; }

    const uint32_t sb = smem_to_u32(smem);
    const uint32_t STG = 49152;  // per-stage: A 0 | B_HI 16384 | B_LO 32768
    const int tid = threadIdx.x, lane = tid & 31, wid = tid >> 5;
    const int warpM = wid & 1, warpN = wid >> 1;
    const int m0 = blockIdx.y * 128, n0 = blockIdx.x * 128;
    const int r = tid >> 1, cb2 = (tid & 1);  // each row split between 2 threads

    float c[4][4][4];
#pragma unroll
    for (int i = 0; i < 4; i++)
#pragma unroll
        for (int j = 0; j < 4; j++)
#pragma unroll
            for (int l = 0; l < 4; l++) c[i][j][l] = 0.f;

    auto do_stage = [&](int kc) {
        const int k0 = kc << 6;
        const uint32_t bufo = (uint32_t)(kc & 1) * STG;
        uint32_t rb = (uint32_t)r * 128u + (uint32_t)cb2 * 64u;
        {
            int grow = m0 + r;
            const __half* srcp = A16 + (size_t)grow * HH + k0 + cb2 * 32;
            int sz = (grow < M) ? 16 : 0;
#pragma unroll
            for (int i = 0; i < 4; i++)
                cp16z(sb + bufo + swz(rb + i * 16u), srcp + i * 8, sz);
        }
        {
            const __half* sh = wh + (size_t)(n0 + r) * HH + k0 + cb2 * 32;
            const __half* sl = wl + (size_t)(n0 + r) * HH + k0 + cb2 * 32;
#pragma unroll
            for (int i = 0; i < 4; i++) {
                cp_async16(sb + bufo + 16384u + swz(rb + i * 16u), sh + i * 8);
                cp_async16(sb + bufo + 32768u + swz(rb + i * 16u), sl + i * 8);
            }
        }
        cp_commit();
    };

    do_stage(0);
    do_stage(1);

    for (int kc = 0; kc < 4; kc++) {
        if (kc < 3) cp_wait<1>(); else cp_wait<0>();
        __syncthreads();
        const uint32_t bufo = (uint32_t)(kc & 1) * STG;
#pragma unroll
        for (int ks = 0; ks < 4; ks++) {
            uint32_t a[4][4];
#pragma unroll
            for (int mt = 0; mt < 4; mt++) {
                int row = warpM * 64 + mt * 16 + (lane & 15);
                uint32_t off = swz((uint32_t)row * 128u + ks * 32u + ((lane >> 4) << 4));
                ldsm_x4(a[mt], sb + bufo + off);
            }
            uint32_t bh[4][2], bl[4][2];
#pragma unroll
            for (int nt = 0; nt < 4; nt++) {
                int n = warpN * 32 + nt * 8 + (lane & 7);
                uint32_t off = swz((uint32_t)n * 128u + ks * 32u + (((lane >> 3) & 1) << 4));
                ldsm_x2(bh[nt], sb + bufo + 16384u + off);
                ldsm_x2(bl[nt], sb + bufo + 32768u + off);
            }
#pragma unroll
            for (int mt = 0; mt < 4; mt++)
#pragma unroll
                for (int nt = 0; nt < 4; nt++) {
                    mma_fp16(c[mt][nt], a[mt], bh[nt]);
                    mma_fp16(c[mt][nt], a[mt], bl[nt]);
                }
        }
        __syncthreads();
        if (kc + 2 < 4) do_stage(kc + 2);
    }

    // ---- epilogue ----
    const int gid = lane >> 2, tig = lane & 3;
#pragma unroll
    for (int mt = 0; mt < 4; mt++)
#pragma unroll
        for (int nt = 0; nt < 4; nt++) {
            int col = n0 + warpN * 32 + nt * 8 + tig * 2;
            float bc0 = bias[col], bc1 = bias[col + 1];
#pragma unroll
            for (int h = 0; h < 2; h++) {
                int row = m0 + warpM * 64 + mt * 16 + gid + h * 8;
                if (row >= M) continue;
                float v0 = c[mt][nt][h * 2 + 0] + bc0;
                float v1 = c[mt][nt][h * 2 + 1] + bc1;
                float* crow = C + (size_t)row * HH + col;
                if (emode == 2) {
                    float l0 = v0 > 0.f ? v0 : 0.01f * v0;
                    float l1 = v1 > 0.f ? v1 : 0.01f * v1;
                    float n0v = crow[0] + l0;
                    float n1v = crow[1] + l1;
                    bool z = (data[row] == 1);
                    *(float2*)crow = z ? make_float2(0.f, 0.f) : make_float2(n0v, n1v);
                    int b = row >> 9, ll = row & (LL - 1);
                    size_t yo = (size_t)(b * LY + 1 + ll) * HH + col;
                    *(__half2*)(y16 + yo) = __halves2half2(__float2half_rn(n0v),
                                                          __float2half_rn(n1v));
                } else {
                    *(float2*)crow = make_float2(v0, v1);
                }
            }
        }
}

// ============ embedding HMMA GEMM (3-pass split-fp16, exact x0) ============
__global__ void __launch_bounds__(256, 2)
gemm_emb_mma_kernel(const int* __restrict__ data, const float* __restrict__ emb,
                    const __half* __restrict__ whE, const __half* __restrict__ wlE,
                    const float* __restrict__ bias, const float* __restrict__ pos,
                    float* __restrict__ C)
{
    extern __shared__ char smem[];
    const uint32_t sb = smem_to_u32(smem);
    const int tid = threadIdx.x, lane = tid & 31, wid = tid >> 5;
    const int warpM = wid & 1, warpN = wid >> 1;
    const int m0 = blockIdx.y * 128, n0 = blockIdx.x * 128;
    const int half = tid >> 7, r = tid & 127;

    float c[4][4][4];
#pragma unroll
    for (int i = 0; i < 4; i++)
#pragma unroll
        for (int j = 0; j < 4; j++)
#pragma unroll
            for (int l = 0; l < 4; l++) c[i][j][l] = 0.f;

    for (int kc = 0; kc < 5; kc++) {
        const int k0 = kc << 6;
        // A: gather fp32, split into fp16 hi/lo (this half's component)
        {
            int grow = m0 + r;
            const float* srow = emb + (size_t)data[grow] * E_DIM;
            char* dbase = smem + half * 16384;
            uint32_t rb = (uint32_t)r * 128u;
#pragma unroll
            for (int i = 0; i < 8; i++) {
                union { uint4 u; unsigned short s[8]; } pk;
#pragma unroll
                for (int j = 0; j < 8; j++) {
                    int kk = k0 + i * 8 + j;
                    float f = (kk < E_DIM) ? srow[kk] : 0.f;
                    __half h, l;
                    split_fp16(f, h, l);
                    pk.s[j] = __half_as_ushort(half ? l : h);
                }
                *(uint4*)(dbase + swz(rb + i * 16u)) = pk.u;
            }
        }
        // B hi/lo
        {
            const __half* srcp = (half ? wlE : whE) + (size_t)(n0 + r) * 320 + k0;
            char* dbase = smem + 32768 + half * 16384;
            uint32_t rb = (uint32_t)r * 128u;
#pragma unroll
            for (int i = 0; i < 8; i++)
                *(uint4*)(dbase + swz(rb + i * 16u)) = *(const uint4*)(srcp + i * 8);
        }
        __syncthreads();
#pragma unroll
        for (int ks = 0; ks < 4; ks++) {
            uint32_t ah[4][4], al[4][4];
#pragma unroll
            for (int mt = 0; mt < 4; mt++) {
                int row = warpM * 64 + mt * 16 + (lane & 15);
                uint32_t off = swz((uint32_t)row * 128u + ks * 32u + ((lane >> 4) << 4));
                ldsm_x4(ah[mt], sb + off);
                ldsm_x4(al[mt], sb + 16384u + off);
            }
            uint32_t bh[4][2], bl[4][2];
#pragma unroll
            for (int nt = 0; nt < 4; nt++) {
                int n = warpN * 32 + nt * 8 + (lane & 7);
                uint32_t off = swz((uint32_t)n * 128u + ks * 32u + (((lane >> 3) & 1) << 4));
                ldsm_x2(bh[nt], sb + 32768u + off);
                ldsm_x2(bl[nt], sb + 49152u + off);
            }
#pragma unroll
            for (int mt = 0; mt < 4; mt++)
#pragma unroll
                for (int nt = 0; nt < 4; nt++) {
                    mma_fp16(c[mt][nt], ah[mt], bh[nt]);
                    mma_fp16(c[mt][nt], ah[mt], bl[nt]);
                    mma_fp16(c[mt][nt], al[mt], bh[nt]);
                }
        }
        __syncthreads();
    }

    const int gid = lane >> 2, tig = lane & 3;
#pragma unroll
    for (int mt = 0; mt < 4; mt++)
#pragma unroll
        for (int nt = 0; nt < 4; nt++) {
            int col = n0 + warpN * 32 + nt * 8 + tig * 2;
            float bc0 = bias[col], bc1 = bias[col + 1];
#pragma unroll
            for (int h = 0; h < 2; h++) {
                int row = m0 + warpM * 64 + mt * 16 + gid + h * 8;
                int pr = (row & (LL - 1)) * HH + col;
                float v0 = c[mt][nt][h * 2 + 0] + bc0 + pos[pr];
                float v1 = c[mt][nt][h * 2 + 1] + bc1 + pos[pr + 1];
                *(float2*)&C[(size_t)row * HH + col] = make_float2(v0, v1);
            }
        }
}

// ============ weight prep: coalesced tiled transpose + fp16 split ============
__global__ void prep_w_kernel(const float* __restrict__ rWQ, const float* __restrict__ rWK,
                              const float* __restrict__ rWO, const float* __restrict__ sWK,
                              const float* __restrict__ sWV, const float* __restrict__ embW,
                              __half* __restrict__ whi, __half* __restrict__ wlo,
                              __half* __restrict__ whiE, __half* __restrict__ wloE)
{
    int slot = blockIdx.z;
    int n0 = blockIdx.x * 32, k0 = blockIdx.y * 32;
    const float* W; int K, Kpad;
    __half *oh, *ol;
    if (slot < 30) {
        if (k0 >= 256) return;
        int fam = slot / 6, it = slot % 6;
        W = (fam == 0 ? rWQ : fam == 1 ? rWK : fam == 2 ? rWO :
             fam == 3 ? sWK : sWV) + (size_t)it * HH * HH;
        K = 256; Kpad = 256;
        oh = whi + (size_t)slot * 65536; ol = wlo + (size_t)slot * 65536;
    } else {
        W = embW; K = E_DIM; Kpad = 320; oh = whiE; ol = wloE;
    }
    __shared__ float tile[32][33];
    int tx = threadIdx.x, ty = threadIdx.y;
#pragma unroll
    for (int i = 0; i < 4; i++) {
        int k = k0 + ty + i * 8;
        tile[ty + i * 8][tx] = (k < K) ? W[(size_t)k * HH + n0 + tx] : 0.f;
    }
    __syncthreads();
#pragma unroll
    for (int i = 0; i < 4; i++) {
        int n = n0 + ty + i * 8;
        float x = tile[tx][ty + i * 8];
        __half h, l;
        split_fp16(x, h, l);
        size_t o = (size_t)n * Kpad + k0 + tx;
        oh[o] = h; ol[o] = l;
    }
}

// ---------------- layernorm: one warp per row -> fp16 out ----------------
__global__ void __launch_bounds__(256)
layernorm_kernel(const float* __restrict__ x, __half* __restrict__ y16,
                 const float* __restrict__ g, const float* __restrict__ b)
{
    int w = threadIdx.x >> 5, lane = threadIdx.x & 31;
    int row = blockIdx.x * 8 + w;
    const float* xr = x + (size_t)row * HH;
    float4 v0 = *(const float4*)&xr[lane * 4];
    float4 v1 = *(const float4*)&xr[lane * 4 + 128];
    float s = v0.x + v0.y + v0.z + v0.w + v1.x + v1.y + v1.z + v1.w;
    float mean = warpReduceSum(s) * (1.f / HH);
    float d[8] = { v0.x - mean, v0.y - mean, v0.z - mean, v0.w - mean,
                   v1.x - mean, v1.y - mean, v1.z - mean, v1.w - mean };
    float s2 = 0.f;
#pragma unroll
    for (int i = 0; i < 8; i++) s2 += d[i] * d[i];
    float var = warpReduceSum(s2) * (1.f / HH);
    float rs = rsqrtf(var + 1e-5f);
    float4 g0 = *(const float4*)&g[lane * 4];
    float4 g1 = *(const float4*)&g[lane * 4 + 128];
    float4 bb0 = *(const float4*)&b[lane * 4];
    float4 bb1 = *(const float4*)&b[lane * 4 + 128];
    float o[8] = { g0.x*d[0]*rs + bb0.x, g0.y*d[1]*rs + bb0.y,
                   g0.z*d[2]*rs + bb0.z, g0.w*d[3]*rs + bb0.w,
                   g1.x*d[4]*rs + bb1.x, g1.y*d[5]*rs + bb1.y,
                   g1.z*d[6]*rs + bb1.z, g1.w*d[7]*rs + bb1.w };
#pragma unroll
    for (int seg = 0; seg < 2; seg++) {
        ushort4 hv;
        hv.x = __half_as_ushort(__float2half_rn(o[seg*4+0]));
        hv.y = __half_as_ushort(__float2half_rn(o[seg*4+1]));
        hv.z = __half_as_ushort(__float2half_rn(o[seg*4+2]));
        hv.w = __half_as_ushort(__float2half_rn(o[seg*4+3]));
        *(ushort4*)(y16 + (size_t)row * HH + lane * 4 + seg * 128) = hv;
    }
}

// ---------------- relay = mean over L ----------------
__global__ void __launch_bounds__(256)
relay_mean_kernel(const float* __restrict__ x0, float* __restrict__ relay)
{
    int b = blockIdx.x;
    int tx = threadIdx.x & 63, ty = threadIdx.x >> 6;
    float4 acc = make_float4(0.f, 0.f, 0.f, 0.f);
    for (int l = ty; l < LL; l += 4) {
        float4 v = *(const float4*)&x0[(size_t)(b * LL + l) * HH + tx * 4];
        acc.x += v.x; acc.y += v.y; acc.z += v.z; acc.w += v.w;
    }
    __shared__ float4 part[4][64];
    part[ty][tx] = acc;
    __syncthreads();
    if (ty == 0) {
        float4 s = part[0][tx];
#pragma unroll
        for (int i = 1; i < 4; i++) {
            s.x += part[i][tx].x; s.y += part[i][tx].y;
            s.z += part[i][tx].z; s.w += part[i][tx].w;
        }
        const float inv = 1.f / LL;
        *(float4*)&relay[b * HH + tx * 4] =
            make_float4(s.x * inv, s.y * inv, s.z * inv, s.w * inv);
    }
}

// ---------------- fused relay projections: ak, av, q2, y-row ----------------
__global__ void __launch_bounds__(256)
rowproj4_kernel(const float* __restrict__ relay,
                const float* __restrict__ WK, const float* __restrict__ bK, float* __restrict__ ak,
                const float* __restrict__ WV, const float* __restrict__ bV, float* __restrict__ av,
                const float* __restrict__ sWQ, const float* __restrict__ sbQ, float* __restrict__ q2,
                __half* __restrict__ y16)
{
    int seg = blockIdx.x >> 5, b = blockIdx.x & 31, t = threadIdx.x;
    if (seg == 3) {
        y16[(size_t)(b * LY) * HH + t] = __float2half_rn(relay[b * HH + t]);
        return;
    }
    const float* W  = seg == 0 ? WK : seg == 1 ? WV : sWQ;
    const float* bi = seg == 0 ? bK : seg == 1 ? bV : sbQ;
    float* o        = seg == 0 ? ak : seg == 1 ? av : q2;
    __shared__ float xin[HH];
    xin[t] = relay[b * HH + t];
    __syncthreads();
    float s = bi[t];
#pragma unroll 8
    for (int k = 0; k < HH; k++) s += xin[k] * W[k * HH + t];
    o[b * HH + t] = s;
}

__global__ void rowproj_kernel(const float* __restrict__ in, const float* __restrict__ W,
                               const float* __restrict__ bias, float* __restrict__ out,
                               int lrelu)
{
    __shared__ float xin[HH];
    int b = blockIdx.x, t = threadIdx.x;
    xin[t] = in[b * HH + t];
    __syncthreads();
    float s = bias[t];
#pragma unroll 8
    for (int k = 0; k < HH; k++) s += xin[k] * W[k * HH + t];
    if (lrelu) s = s > 0.f ? s : 0.01f * s;
    out[b * HH + t] = s;
}

// ---------------- msa1 windowed attention -> fp16 att ----------------
__global__ void __launch_bounds__(256)
msa1_attn_kernel(const float* __restrict__ q, const float* __restrict__ k,
                 const float* __restrict__ ak, const float* __restrict__ av,
                 __half* __restrict__ att16)
{
    int row = blockIdx.x;
    int b = row >> 9, l = row & (LL - 1);
    int t = threadIdx.x;
    int c = t;
    float qv  = q[(size_t)row * HH + c];
    float k0v = k[(size_t)row * HH + c];
    float kmv = (l > 0)      ? k[(size_t)(row - 1) * HH + c] : 0.f;
    float kpv = (l < LL - 1) ? k[(size_t)(row + 1) * HH + c] : 0.f;
    float akv = ak[b * HH + c];
    float avv = av[b * HH + c];
    const float sc = 0.17677669529663687f;
    float s0 = warpReduceSum(qv * akv) * sc;
    float s1 = warpReduceSum(qv * kmv) * sc;
    float s2 = warpReduceSum(qv * k0v) * sc;
    float s3 = warpReduceSum(qv * kpv) * sc;
    float m = fmaxf(fmaxf(s0, s1), fmaxf(s2, s3));
    float e0 = expf(s0 - m), e1 = expf(s1 - m), e2 = expf(s2 - m), e3 = expf(s3 - m);
    float inv = 1.f / (e0 + e1 + e2 + e3);
    float o = (e0 * avv + e1 * kmv + e2 * k0v + e3 * kpv) * inv;
    att16[(size_t)row * HH + c] = __float2half_rn(o);
}

// ---------------- msa2 ----------------
__global__ void __launch_bounds__(256)
msa2_attn_kernel(const float* __restrict__ q2, const float* __restrict__ yk,
                 const float* __restrict__ yv, float* __restrict__ att2)
{
    __shared__ float sc[LY];
    __shared__ float red[8];
    __shared__ float part[8][HD];
    int b = blockIdx.x >> 3, h = blockIdx.x & 7;
    int t = threadIdx.x, w = t >> 5, d = t & 31;
    const float scale = 0.17677669529663687f;
    float qv = q2[b * HH + h * HD + d];
    const float* kb = yk + (size_t)b * LY * HH + h * HD;
    const float* vb = yv + (size_t)b * LY * HH + h * HD;
    for (int l = w; l < LY; l += 8) {
        float s = warpReduceSum(qv * kb[(size_t)l * HH + d]) * scale;
        if (d == 0) sc[l] = s;
    }
    __syncthreads();
    float m = -3.4e38f;
    for (int l = t; l < LY; l += 256) m = fmaxf(m, sc[l]);
#pragma unroll
    for (int o = 16; o > 0; o >>= 1) m = fmaxf(m, __shfl_xor_sync(0xffffffffu, m, o));
    if (d == 0) red[w] = m;
    __syncthreads();
    float mm = red[0];
#pragma unroll
    for (int i = 1; i < 8; i++) mm = fmaxf(mm, red[i]);
    __syncthreads();
    float ssum = 0.f;
    for (int l = t; l < LY; l += 256) { float e = expf(sc[l] - mm); sc[l] = e; ssum += e; }
    ssum = warpReduceSum(ssum);
    if (d == 0) red[w] = ssum;
    __syncthreads();
    float tot = 0.f;
#pragma unroll
    for (int i = 0; i < 8; i++) tot += red[i];
    float acc = 0.f;
    for (int l = w; l < LY; l += 8) acc += sc[l] * vb[(size_t)l * HH + d];
    part[w][d] = acc;
    __syncthreads();
    if (w == 0) {
        float o = 0.f;
#pragma unroll
        for (int i = 0; i < 8; i++) o += part[i][d];
        att2[b * HH + h * HD + d] = o / tot;
    }
}

// ---------------- final: 0.5*max_l(nodes) + 0.5*relay ----------------
__global__ void __launch_bounds__(256)
final_kernel(const float* __restrict__ nodes, const float* __restrict__ relay,
             float* __restrict__ out)
{
    int b = blockIdx.x;
    int tx = threadIdx.x & 63, ty = threadIdx.x >> 6;
    float4 m = make_float4(-3.4e38f, -3.4e38f, -3.4e38f, -3.4e38f);
    for (int l = ty; l < LL; l += 4) {
        float4 v = *(const float4*)&nodes[(size_t)(b * LL + l) * HH + tx * 4];
        m.x = fmaxf(m.x, v.x); m.y = fmaxf(m.y, v.y);
        m.z = fmaxf(m.z, v.z); m.w = fmaxf(m.w, v.w);
    }
    __shared__ float4 part[4][64];
    part[ty][tx] = m;
    __syncthreads();
    if (ty == 0) {
        float4 s = part[0][tx];
#pragma unroll
        for (int i = 1; i < 4; i++) {
            s.x = fmaxf(s.x, part[i][tx].x); s.y = fmaxf(s.y, part[i][tx].y);
            s.z = fmaxf(s.z, part[i][tx].z); s.w = fmaxf(s.w, part[i][tx].w);
        }
        float4 r = *(const float4*)&relay[b * HH + tx * 4];
        *(float4*)&out[b * HH + tx * 4] =
            make_float4(0.5f * s.x + 0.5f * r.x, 0.5f * s.y + 0.5f * r.y,
                        0.5f * s.z + 0.5f * r.z, 0.5f * s.w + 0.5f * r.w);
    }
}

// ---------------- host ----------------
extern "C" void kernel_launch(void* const* d_in, const int* in_sizes, int n_in,
                              void* d_out, int out_size)
{
    const int*   data     = (const int*)  d_in[0];
    const float* emb      = (const float*)d_in[1];
    const float* emb_fc_W = (const float*)d_in[2];
    const float* emb_fc_b = (const float*)d_in[3];
    const float* pos_emb  = (const float*)d_in[4];
    const float* ln_g     = (const float*)d_in[5];
    const float* ln_b     = (const float*)d_in[6];
    const float* r_WQ = (const float*)d_in[7];
    const float* r_bQ = (const float*)d_in[8];
    const float* r_WK = (const float*)d_in[9];
    const float* r_bK = (const float*)d_in[10];
    const float* r_WV = (const float*)d_in[11];
    const float* r_bV = (const float*)d_in[12];
    const float* r_WO = (const float*)d_in[13];
    const float* r_bO = (const float*)d_in[14];
    const float* s_WQ = (const float*)d_in[15];
    const float* s_bQ = (const float*)d_in[16];
    const float* s_WK = (const float*)d_in[17];
    const float* s_bK = (const float*)d_in[18];
    const float* s_WV = (const float*)d_in[19];
    const float* s_bV = (const float*)d_in[20];
    const float* s_WO = (const float*)d_in[21];
    const float* s_bO = (const float*)d_in[22];
    float* out = (float*)d_out;
    (void)in_sizes; (void)n_in; (void)out_size;

    float *nodes, *q, *k, *yk, *yv, *relay, *ak, *av, *q2, *att2;
    __half *w16h, *w16l, *wEh, *wEl, *nln16, *att16, *y16;
    cudaGetSymbolAddress((void**)&nodes, g_nodes);
    cudaGetSymbolAddress((void**)&q,     g_q);
    cudaGetSymbolAddress((void**)&k,     g_k);
    cudaGetSymbolAddress((void**)&yk,    g_yk);
    cudaGetSymbolAddress((void**)&yv,    g_yv);
    cudaGetSymbolAddress((void**)&relay, g_relay);
    cudaGetSymbolAddress((void**)&ak,    g_ak);
    cudaGetSymbolAddress((void**)&av,    g_av);
    cudaGetSymbolAddress((void**)&q2,    g_q2);
    cudaGetSymbolAddress((void**)&att2,  g_att2);
    cudaGetSymbolAddress((void**)&w16h,  g_w16h);
    cudaGetSymbolAddress((void**)&w16l,  g_w16l);
    cudaGetSymbolAddress((void**)&wEh,   g_wEh);
    cudaGetSymbolAddress((void**)&wEl,   g_wEl);
    cudaGetSymbolAddress((void**)&nln16, g_nln16);
    cudaGetSymbolAddress((void**)&att16, g_att16);
    cudaGetSymbolAddress((void**)&y16,   g_y16);

    const int M1 = BB * LL;    // 16384
    const int M2 = BB * LY;    // 16416
    const int MMA_SMEM  = 98304;   // 2 x 48KB stages -> 2 blocks/SM
    const int EMB_SMEM  = 65536;
    static int attr_done = 0;
    if (!attr_done) {
        cudaFuncSetAttribute(gemm_mma_kernel,
                             cudaFuncAttributeMaxDynamicSharedMemorySize, MMA_SMEM);
        cudaFuncSetAttribute(gemm_emb_mma_kernel,
                             cudaFuncAttributeMaxDynamicSharedMemorySize, EMB_SMEM);
        attr_done = 1;
    }

    dim3 blk(256);
    auto WHp = [&](int slot) { return w16h + (size_t)slot * 65536; };
    auto WLp = [&](int slot) { return w16l + (size_t)slot * 65536; };

    // prep split-transposed weights (slots: Q=0..5, K=6..11, O=12..17, sK=18..23, sV=24..29, emb=30)
    prep_w_kernel<<<dim3(8, 10, 31), dim3(32, 8)>>>(r_WQ, r_WK, r_WO, s_WK, s_WV, emb_fc_W,
                                                    w16h, w16l, wEh, wEl);

    // x0 = emb[data] @ emb_fc_W + b + pos ; relay = mean_L(x0)
    gemm_emb_mma_kernel<<<dim3(2, 128), blk, EMB_SMEM>>>(data, emb, wEh, wEl,
                                                         emb_fc_b, pos_emb, nodes);
    relay_mean_kernel<<<BB, blk>>>(nodes, relay);

    for (int i = 0; i < ITERS; i++) {
        const float* bQ = r_bQ + i * HH;
        const float* bK = r_bK + i * HH;
        const float* WK = r_WK + i * HH * HH;
        const float* WV = r_WV + i * HH * HH;
        const float* bV = r_bV + i * HH;
        const float* bO = r_bO + i * HH;
        const float* sWQ = s_WQ + i * HH * HH; const float* sbQ = s_bQ + i * HH;
        const float* sbK = s_bK + i * HH;
        const float* sbV = s_bV + i * HH;
        const float* sWO = s_WO + i * HH * HH; const float* sbO = s_bO + i * HH;

        layernorm_kernel<<<M1 / 8, blk>>>(nodes, nln16, ln_g + i * HH, ln_b + i * HH);
        // fused Q + K projections
        gemm_mma_kernel<<<dim3(2, 128, 2), blk, MMA_SMEM>>>(
            nln16, WHp(i), WLp(i), bQ, q, WHp(6 + i), WLp(6 + i), bK, k,
            M1, 0, nullptr, nullptr);
        // fused ak + av + q2 + relay->y row
        rowproj4_kernel<<<4 * BB, blk>>>(relay, WK, bK, ak, WV, bV, av,
                                         sWQ, sbQ, q2, y16);
        msa1_attn_kernel<<<M1, blk>>>(q, k, ak, av, att16);
        // O projection + leaky residual + mask + y emit
        gemm_mma_kernel<<<dim3(2, 128, 1), blk, MMA_SMEM>>>(
            att16, WHp(12 + i), WLp(12 + i), bO, nodes,
            nullptr, nullptr, nullptr, nullptr,
            M1, 2, data, y16);
        // fused yK + yV
        gemm_mma_kernel<<<dim3(2, 129, 2), blk, MMA_SMEM>>>(
            y16, WHp(18 + i), WLp(18 + i), sbK, yk,
            WHp(24 + i), WLp(24 + i), sbV, yv,
            M2, 0, nullptr, nullptr);
        msa2_attn_kernel<<<BB * NH, blk>>>(q2, yk, yv, att2);
        rowproj_kernel<<<BB, HH>>>(att2, sWO, sbO, relay, 1);
    }
    final_kernel<<<BB, blk>>>(nodes, relay, out);
}

// round 12
// speedup vs baseline: 3.2621x; 1.0257x over previous
#include <cuda_runtime.h>
#include <cuda_fp16.h>
#include <math.h>
#include <cstdint>

#define BB   32
#define LL   512
#define HH   256
#define NH   8
#define HD   32
#define ITERS 6
#define E_DIM 300
#define LY   513  /* 1 + L */

typedef unsigned long long ull;

// ---------------- scratch (device globals; no allocation) ----------------
__device__ float g_nodes[BB*LL*HH];
__device__ float g_relay[BB*HH];
__device__ float g_ak   [BB*HH];
__device__ float g_av   [BB*HH];
__device__ float g_q2   [BB*HH];
__device__ float g_att2 [BB*HH];
// fp16 activations
__device__ __align__(16) __half g_q16  [BB*LL*HH];
__device__ __align__(16) __half g_k16  [BB*LL*HH];
__device__ __align__(16) __half g_yk16 [BB*LY*HH];
__device__ __align__(16) __half g_yv16 [BB*LY*HH];
__device__ __align__(16) __half g_nln16[BB*LL*HH];
__device__ __align__(16) __half g_att16[BB*LL*HH];
__device__ __align__(16) __half g_y16  [BB*LY*HH];
// split-fp16 transposed weights: 30 slots of [256 n][256 k]
__device__ __align__(16) __half g_w16h[30*65536];
__device__ __align__(16) __half g_w16l[30*65536];
// emb_fc split-transposed: [256 n][320 k] (zero-padded k>=300)
__device__ __align__(16) __half g_wEh[256*320];
__device__ __align__(16) __half g_wEl[256*320];

// ---------------- helpers ----------------
__device__ __forceinline__ float warpReduceSum(float v) {
#pragma unroll
    for (int o = 16; o > 0; o >>= 1) v += __shfl_xor_sync(0xffffffffu, v, o);
    return v;
}
__device__ __forceinline__ uint32_t smem_to_u32(const void* p) {
    uint32_t a;
    asm("{ .reg .u64 t; cvta.to.shared.u64 t, %1; cvt.u32.u64 %0, t; }" : "=r"(a) : "l"(p));
    return a;
}
__device__ __forceinline__ uint32_t swz(uint32_t x) { return x ^ ((x >> 3) & 0x70); }

__device__ __forceinline__ void ldsm_x4(uint32_t* r, uint32_t addr) {
    asm volatile("ldmatrix.sync.aligned.m8n8.x4.shared.b16 {%0,%1,%2,%3}, [%4];"
                 : "=r"(r[0]), "=r"(r[1]), "=r"(r[2]), "=r"(r[3]) : "r"(addr));
}
__device__ __forceinline__ void ldsm_x2(uint32_t* r, uint32_t addr) {
    asm volatile("ldmatrix.sync.aligned.m8n8.x2.shared.b16 {%0,%1}, [%2];"
                 : "=r"(r[0]), "=r"(r[1]) : "r"(addr));
}
__device__ __forceinline__ void mma_fp16(float* c, const uint32_t* a, const uint32_t* b) {
    asm volatile("mma.sync.aligned.m16n8k16.row.col.f32.f16.f16.f32 "
                 "{%0,%1,%2,%3}, {%4,%5,%6,%7}, {%8,%9}, {%0,%1,%2,%3};"
                 : "+f"(c[0]), "+f"(c[1]), "+f"(c[2]), "+f"(c[3])
                 : "r"(a[0]), "r"(a[1]), "r"(a[2]), "r"(a[3]), "r"(b[0]), "r"(b[1]));
}
__device__ __forceinline__ void split_fp16(float v, __half& h, __half& l) {
    h = __float2half_rn(v);
    l = __float2half_rn(v - __half2float(h));
}
__device__ __forceinline__ void cp_async16(uint32_t dst, const void* src) {
    asm volatile("cp.async.cg.shared.global [%0], [%1], 16;" :: "r"(dst), "l"(src));
}
__device__ __forceinline__ void cp16z(uint32_t dst, const void* src, int sz) {
    asm volatile("cp.async.cg.shared.global [%0], [%1], 16, %2;"
                 :: "r"(dst), "l"(src), "r"(sz));
}
__device__ __forceinline__ void cp_commit() {
    asm volatile("cp.async.commit_group;" ::: "memory");
}
template<int N> __device__ __forceinline__ void cp_wait() {
    asm volatile("cp.async.wait_group %0;" :: "n"(N) : "memory");
}

// ============ HMMA fp16 2-pass GEMM (double-buffered cp.async, 2 blocks/SM) ============
// out: emode 0 -> C16 = fp16(acc + bias)
//      emode 2 -> nodes(C0 fp32) += leaky_relu(acc+bias), masked by data; y fp16 pre-mask
// blockIdx.z==1 -> second problem.
__global__ void __launch_bounds__(256, 2)
gemm_mma_kernel(const __half* __restrict__ A16,
                const __half* __restrict__ wh0, const __half* __restrict__ wl0,
                const float* __restrict__ b0, void* __restrict__ C0,
                const __half* __restrict__ wh1, const __half* __restrict__ wl1,
                const float* __restrict__ b1, void* __restrict__ C1,
                int M, int emode, const int* __restrict__ data,
                __half* __restrict__ y16)
{
    extern __shared__ char smem[];
    const __half* wh = wh0; const __half* wl = wl0;
    const float* bias = b0; void* C = C0;
    if (blockIdx.z == 1) { wh = wh1; wl = wl1; bias = b1; C = C1; }

    const uint32_t sb = smem_to_u32(smem);
    const uint32_t STG = 49152;  // per-stage: A 0 | B_HI 16384 | B_LO 32768
    const int tid = threadIdx.x, lane = tid & 31, wid = tid >> 5;
    const int warpM = wid & 1, warpN = wid >> 1;
    const int m0 = blockIdx.y * 128, n0 = blockIdx.x * 128;
    const int r = tid >> 1, cb2 = (tid & 1);

    float c[4][4][4];
#pragma unroll
    for (int i = 0; i < 4; i++)
#pragma unroll
        for (int j = 0; j < 4; j++)
#pragma unroll
            for (int l = 0; l < 4; l++) c[i][j][l] = 0.f;

    auto do_stage = [&](int kc) {
        const int k0 = kc << 6;
        const uint32_t bufo = (uint32_t)(kc & 1) * STG;
        uint32_t rb = (uint32_t)r * 128u + (uint32_t)cb2 * 64u;
        {
            int grow = m0 + r;
            const __half* srcp = A16 + (size_t)grow * HH + k0 + cb2 * 32;
            int sz = (grow < M) ? 16 : 0;
#pragma unroll
            for (int i = 0; i < 4; i++)
                cp16z(sb + bufo + swz(rb + i * 16u), srcp + i * 8, sz);
        }
        {
            const __half* sh = wh + (size_t)(n0 + r) * HH + k0 + cb2 * 32;
            const __half* sl = wl + (size_t)(n0 + r) * HH + k0 + cb2 * 32;
#pragma unroll
            for (int i = 0; i < 4; i++) {
                cp_async16(sb + bufo + 16384u + swz(rb + i * 16u), sh + i * 8);
                cp_async16(sb + bufo + 32768u + swz(rb + i * 16u), sl + i * 8);
            }
        }
        cp_commit();
    };

    do_stage(0);
    do_stage(1);

    for (int kc = 0; kc < 4; kc++) {
        if (kc < 3) cp_wait<1>(); else cp_wait<0>();
        __syncthreads();
        const uint32_t bufo = (uint32_t)(kc & 1) * STG;
#pragma unroll
        for (int ks = 0; ks < 4; ks++) {
            uint32_t a[4][4];
#pragma unroll
            for (int mt = 0; mt < 4; mt++) {
                int row = warpM * 64 + mt * 16 + (lane & 15);
                uint32_t off = swz((uint32_t)row * 128u + ks * 32u + ((lane >> 4) << 4));
                ldsm_x4(a[mt], sb + bufo + off);
            }
            uint32_t bh[4][2], bl[4][2];
#pragma unroll
            for (int nt = 0; nt < 4; nt++) {
                int n = warpN * 32 + nt * 8 + (lane & 7);
                uint32_t off = swz((uint32_t)n * 128u + ks * 32u + (((lane >> 3) & 1) << 4));
                ldsm_x2(bh[nt], sb + bufo + 16384u + off);
                ldsm_x2(bl[nt], sb + bufo + 32768u + off);
            }
#pragma unroll
            for (int mt = 0; mt < 4; mt++)
#pragma unroll
                for (int nt = 0; nt < 4; nt++) {
                    mma_fp16(c[mt][nt], a[mt], bh[nt]);
                    mma_fp16(c[mt][nt], a[mt], bl[nt]);
                }
        }
        __syncthreads();
        if (kc + 2 < 4) do_stage(kc + 2);
    }

    // ---- epilogue ----
    const int gid = lane >> 2, tig = lane & 3;
#pragma unroll
    for (int mt = 0; mt < 4; mt++)
#pragma unroll
        for (int nt = 0; nt < 4; nt++) {
            int col = n0 + warpN * 32 + nt * 8 + tig * 2;
            float bc0 = bias[col], bc1 = bias[col + 1];
#pragma unroll
            for (int h = 0; h < 2; h++) {
                int row = m0 + warpM * 64 + mt * 16 + gid + h * 8;
                if (row >= M) continue;
                float v0 = c[mt][nt][h * 2 + 0] + bc0;
                float v1 = c[mt][nt][h * 2 + 1] + bc1;
                if (emode == 2) {
                    float* crow = (float*)C + (size_t)row * HH + col;
                    float l0 = v0 > 0.f ? v0 : 0.01f * v0;
                    float l1 = v1 > 0.f ? v1 : 0.01f * v1;
                    float n0v = crow[0] + l0;
                    float n1v = crow[1] + l1;
                    bool z = (data[row] == 1);
                    *(float2*)crow = z ? make_float2(0.f, 0.f) : make_float2(n0v, n1v);
                    int b = row >> 9, ll = row & (LL - 1);
                    size_t yo = (size_t)(b * LY + 1 + ll) * HH + col;
                    *(__half2*)(y16 + yo) = __halves2half2(__float2half_rn(n0v),
                                                          __float2half_rn(n1v));
                } else {
                    *(__half2*)((__half*)C + (size_t)row * HH + col) =
                        __halves2half2(__float2half_rn(v0), __float2half_rn(v1));
                }
            }
        }
}

// ============ embedding HMMA GEMM (3-pass split-fp16, exact x0) ============
__global__ void __launch_bounds__(256, 2)
gemm_emb_mma_kernel(const int* __restrict__ data, const float* __restrict__ emb,
                    const __half* __restrict__ whE, const __half* __restrict__ wlE,
                    const float* __restrict__ bias, const float* __restrict__ pos,
                    float* __restrict__ C)
{
    extern __shared__ char smem[];
    const uint32_t sb = smem_to_u32(smem);
    const int tid = threadIdx.x, lane = tid & 31, wid = tid >> 5;
    const int warpM = wid & 1, warpN = wid >> 1;
    const int m0 = blockIdx.y * 128, n0 = blockIdx.x * 128;
    const int half = tid >> 7, r = tid & 127;

    float c[4][4][4];
#pragma unroll
    for (int i = 0; i < 4; i++)
#pragma unroll
        for (int j = 0; j < 4; j++)
#pragma unroll
            for (int l = 0; l < 4; l++) c[i][j][l] = 0.f;

    for (int kc = 0; kc < 5; kc++) {
        const int k0 = kc << 6;
        {
            int grow = m0 + r;
            const float* srow = emb + (size_t)data[grow] * E_DIM;
            char* dbase = smem + half * 16384;
            uint32_t rb = (uint32_t)r * 128u;
#pragma unroll
            for (int i = 0; i < 8; i++) {
                union { uint4 u; unsigned short s[8]; } pk;
#pragma unroll
                for (int j = 0; j < 8; j++) {
                    int kk = k0 + i * 8 + j;
                    float f = (kk < E_DIM) ? srow[kk] : 0.f;
                    __half h, l;
                    split_fp16(f, h, l);
                    pk.s[j] = __half_as_ushort(half ? l : h);
                }
                *(uint4*)(dbase + swz(rb + i * 16u)) = pk.u;
            }
        }
        {
            const __half* srcp = (half ? wlE : whE) + (size_t)(n0 + r) * 320 + k0;
            char* dbase = smem + 32768 + half * 16384;
            uint32_t rb = (uint32_t)r * 128u;
#pragma unroll
            for (int i = 0; i < 8; i++)
                *(uint4*)(dbase + swz(rb + i * 16u)) = *(const uint4*)(srcp + i * 8);
        }
        __syncthreads();
#pragma unroll
        for (int ks = 0; ks < 4; ks++) {
            uint32_t ah[4][4], al[4][4];
#pragma unroll
            for (int mt = 0; mt < 4; mt++) {
                int row = warpM * 64 + mt * 16 + (lane & 15);
                uint32_t off = swz((uint32_t)row * 128u + ks * 32u + ((lane >> 4) << 4));
                ldsm_x4(ah[mt], sb + off);
                ldsm_x4(al[mt], sb + 16384u + off);
            }
            uint32_t bh[4][2], bl[4][2];
#pragma unroll
            for (int nt = 0; nt < 4; nt++) {
                int n = warpN * 32 + nt * 8 + (lane & 7);
                uint32_t off = swz((uint32_t)n * 128u + ks * 32u + (((lane >> 3) & 1) << 4));
                ldsm_x2(bh[nt], sb + 32768u + off);
                ldsm_x2(bl[nt], sb + 49152u + off);
            }
#pragma unroll
            for (int mt = 0; mt < 4; mt++)
#pragma unroll
                for (int nt = 0; nt < 4; nt++) {
                    mma_fp16(c[mt][nt], ah[mt], bh[nt]);
                    mma_fp16(c[mt][nt], ah[mt], bl[nt]);
                    mma_fp16(c[mt][nt], al[mt], bh[nt]);
                }
        }
        __syncthreads();
    }

    const int gid = lane >> 2, tig = lane & 3;
#pragma unroll
    for (int mt = 0; mt < 4; mt++)
#pragma unroll
        for (int nt = 0; nt < 4; nt++) {
            int col = n0 + warpN * 32 + nt * 8 + tig * 2;
            float bc0 = bias[col], bc1 = bias[col + 1];
#pragma unroll
            for (int h = 0; h < 2; h++) {
                int row = m0 + warpM * 64 + mt * 16 + gid + h * 8;
                int pr = (row & (LL - 1)) * HH + col;
                float v0 = c[mt][nt][h * 2 + 0] + bc0 + pos[pr];
                float v1 = c[mt][nt][h * 2 + 1] + bc1 + pos[pr + 1];
                *(float2*)&C[(size_t)row * HH + col] = make_float2(v0, v1);
            }
        }
}

// ============ weight prep: coalesced tiled transpose + fp16 split ============
__global__ void prep_w_kernel(const float* __restrict__ rWQ, const float* __restrict__ rWK,
                              const float* __restrict__ rWO, const float* __restrict__ sWK,
                              const float* __restrict__ sWV, const float* __restrict__ embW,
                              __half* __restrict__ whi, __half* __restrict__ wlo,
                              __half* __restrict__ whiE, __half* __restrict__ wloE)
{
    int slot = blockIdx.z;
    int n0 = blockIdx.x * 32, k0 = blockIdx.y * 32;
    const float* W; int K, Kpad;
    __half *oh, *ol;
    if (slot < 30) {
        if (k0 >= 256) return;
        int fam = slot / 6, it = slot % 6;
        W = (fam == 0 ? rWQ : fam == 1 ? rWK : fam == 2 ? rWO :
             fam == 3 ? sWK : sWV) + (size_t)it * HH * HH;
        K = 256; Kpad = 256;
        oh = whi + (size_t)slot * 65536; ol = wlo + (size_t)slot * 65536;
    } else {
        W = embW; K = E_DIM; Kpad = 320; oh = whiE; ol = wloE;
    }
    __shared__ float tile[32][33];
    int tx = threadIdx.x, ty = threadIdx.y;
#pragma unroll
    for (int i = 0; i < 4; i++) {
        int k = k0 + ty + i * 8;
        tile[ty + i * 8][tx] = (k < K) ? W[(size_t)k * HH + n0 + tx] : 0.f;
    }
    __syncthreads();
#pragma unroll
    for (int i = 0; i < 4; i++) {
        int n = n0 + ty + i * 8;
        float x = tile[tx][ty + i * 8];
        __half h, l;
        split_fp16(x, h, l);
        size_t o = (size_t)n * Kpad + k0 + tx;
        oh[o] = h; ol[o] = l;
    }
}

// ---------------- fused: layernorm (blocks 0..2047) + relay projections (2048..2175) ----
__global__ void __launch_bounds__(256)
ln_rp4_kernel(const float* __restrict__ x, __half* __restrict__ nln16,
              const float* __restrict__ g, const float* __restrict__ b,
              const float* __restrict__ relay,
              const float* __restrict__ WK, const float* __restrict__ bK, float* __restrict__ ak,
              const float* __restrict__ WV, const float* __restrict__ bV, float* __restrict__ av,
              const float* __restrict__ sWQ, const float* __restrict__ sbQ, float* __restrict__ q2,
              __half* __restrict__ y16)
{
    if (blockIdx.x >= 2048) {
        int idx = blockIdx.x - 2048;
        int seg = idx >> 5, bb = idx & 31, t = threadIdx.x;
        if (seg == 3) {
            y16[(size_t)(bb * LY) * HH + t] = __float2half_rn(relay[bb * HH + t]);
            return;
        }
        const float* W  = seg == 0 ? WK : seg == 1 ? WV : sWQ;
        const float* bi = seg == 0 ? bK : seg == 1 ? bV : sbQ;
        float* o        = seg == 0 ? ak : seg == 1 ? av : q2;
        __shared__ float xin[HH];
        xin[t] = relay[bb * HH + t];
        __syncthreads();
        float s = bi[t];
#pragma unroll 8
        for (int k = 0; k < HH; k++) s += xin[k] * W[k * HH + t];
        o[bb * HH + t] = s;
        return;
    }
    int w = threadIdx.x >> 5, lane = threadIdx.x & 31;
    int row = blockIdx.x * 8 + w;
    const float* xr = x + (size_t)row * HH;
    float4 v0 = *(const float4*)&xr[lane * 4];
    float4 v1 = *(const float4*)&xr[lane * 4 + 128];
    float s = v0.x + v0.y + v0.z + v0.w + v1.x + v1.y + v1.z + v1.w;
    float mean = warpReduceSum(s) * (1.f / HH);
    float d[8] = { v0.x - mean, v0.y - mean, v0.z - mean, v0.w - mean,
                   v1.x - mean, v1.y - mean, v1.z - mean, v1.w - mean };
    float s2 = 0.f;
#pragma unroll
    for (int i = 0; i < 8; i++) s2 += d[i] * d[i];
    float var = warpReduceSum(s2) * (1.f / HH);
    float rs = rsqrtf(var + 1e-5f);
    float4 g0 = *(const float4*)&g[lane * 4];
    float4 g1 = *(const float4*)&g[lane * 4 + 128];
    float4 bb0 = *(const float4*)&b[lane * 4];
    float4 bb1 = *(const float4*)&b[lane * 4 + 128];
    float o[8] = { g0.x*d[0]*rs + bb0.x, g0.y*d[1]*rs + bb0.y,
                   g0.z*d[2]*rs + bb0.z, g0.w*d[3]*rs + bb0.w,
                   g1.x*d[4]*rs + bb1.x, g1.y*d[5]*rs + bb1.y,
                   g1.z*d[6]*rs + bb1.z, g1.w*d[7]*rs + bb1.w };
#pragma unroll
    for (int seg = 0; seg < 2; seg++) {
        ushort4 hv;
        hv.x = __half_as_ushort(__float2half_rn(o[seg*4+0]));
        hv.y = __half_as_ushort(__float2half_rn(o[seg*4+1]));
        hv.z = __half_as_ushort(__float2half_rn(o[seg*4+2]));
        hv.w = __half_as_ushort(__float2half_rn(o[seg*4+3]));
        *(ushort4*)(nln16 + (size_t)row * HH + lane * 4 + seg * 128) = hv;
    }
}

// ---------------- relay = mean over L ----------------
__global__ void __launch_bounds__(256)
relay_mean_kernel(const float* __restrict__ x0, float* __restrict__ relay)
{
    int b = blockIdx.x;
    int tx = threadIdx.x & 63, ty = threadIdx.x >> 6;
    float4 acc = make_float4(0.f, 0.f, 0.f, 0.f);
    for (int l = ty; l < LL; l += 4) {
        float4 v = *(const float4*)&x0[(size_t)(b * LL + l) * HH + tx * 4];
        acc.x += v.x; acc.y += v.y; acc.z += v.z; acc.w += v.w;
    }
    __shared__ float4 part[4][64];
    part[ty][tx] = acc;
    __syncthreads();
    if (ty == 0) {
        float4 s = part[0][tx];
#pragma unroll
        for (int i = 1; i < 4; i++) {
            s.x += part[i][tx].x; s.y += part[i][tx].y;
            s.z += part[i][tx].z; s.w += part[i][tx].w;
        }
        const float inv = 1.f / LL;
        *(float4*)&relay[b * HH + tx * 4] =
            make_float4(s.x * inv, s.y * inv, s.z * inv, s.w * inv);
    }
}

__global__ void rowproj_kernel(const float* __restrict__ in, const float* __restrict__ W,
                               const float* __restrict__ bias, float* __restrict__ out,
                               int lrelu)
{
    __shared__ float xin[HH];
    int b = blockIdx.x, t = threadIdx.x;
    xin[t] = in[b * HH + t];
    __syncthreads();
    float s = bias[t];
#pragma unroll 8
    for (int k = 0; k < HH; k++) s += xin[k] * W[k * HH + t];
    if (lrelu) s = s > 0.f ? s : 0.01f * s;
    out[b * HH + t] = s;
}

// ---------------- msa1: 8 rows/block, smem-staged sliding k window ----------------
__global__ void __launch_bounds__(256)
msa1_attn_kernel(const __half* __restrict__ q16, const __half* __restrict__ k16,
                 const float* __restrict__ ak, const float* __restrict__ av,
                 __half* __restrict__ att16)
{
    __shared__ __half ks[10][HH];
    __shared__ __half qs[8][HH];
    __shared__ float aks[HH], avs[HH];
    int r0 = blockIdx.x * 8;
    int b = r0 >> 9, l0 = r0 & (LL - 1);
    int t = threadIdx.x;
    // stage k rows r0-1 .. r0+8 (clamped; guards below handle edges)
    for (int id = t; id < 10 * 128; id += 256) {
        int i = id >> 7, cu = id & 127;
        int gr = r0 - 1 + i;
        gr = gr < 0 ? 0 : (gr > BB * LL - 1 ? BB * LL - 1 : gr);
        ((uint32_t*)ks[i])[cu] = ((const uint32_t*)(k16 + (size_t)gr * HH))[cu];
    }
    for (int id = t; id < 8 * 128; id += 256) {
        int i = id >> 7, cu = id & 127;
        ((uint32_t*)qs[i])[cu] = ((const uint32_t*)(q16 + (size_t)(r0 + i) * HH))[cu];
    }
    aks[t] = ak[b * HH + t];
    avs[t] = av[b * HH + t];
    __syncthreads();
    int c = t;
    float akv = aks[c], avv = avs[c];
    const float sc = 0.17677669529663687f;
#pragma unroll
    for (int rr = 0; rr < 8; rr++) {
        int l = l0 + rr;
        float qv  = __half2float(qs[rr][c]);
        float k0v = __half2float(ks[rr + 1][c]);
        float kmv = (l > 0)      ? __half2float(ks[rr][c])     : 0.f;
        float kpv = (l < LL - 1) ? __half2float(ks[rr + 2][c]) : 0.f;
        float s0 = warpReduceSum(qv * akv) * sc;
        float s1 = warpReduceSum(qv * kmv) * sc;
        float s2 = warpReduceSum(qv * k0v) * sc;
        float s3 = warpReduceSum(qv * kpv) * sc;
        float m = fmaxf(fmaxf(s0, s1), fmaxf(s2, s3));
        float e0 = expf(s0 - m), e1 = expf(s1 - m), e2 = expf(s2 - m), e3 = expf(s3 - m);
        float inv = 1.f / (e0 + e1 + e2 + e3);
        float o = (e0 * avv + e1 * kmv + e2 * k0v + e3 * kpv) * inv;
        att16[(size_t)(r0 + rr) * HH + c] = __float2half_rn(o);
    }
}

// ---------------- msa2 (fp16 yk/yv) ----------------
__global__ void __launch_bounds__(256)
msa2_attn_kernel(const float* __restrict__ q2, const __half* __restrict__ yk,
                 const __half* __restrict__ yv, float* __restrict__ att2)
{
    __shared__ float sc[LY];
    __shared__ float red[8];
    __shared__ float part[8][HD];
    int b = blockIdx.x >> 3, h = blockIdx.x & 7;
    int t = threadIdx.x, w = t >> 5, d = t & 31;
    const float scale = 0.17677669529663687f;
    float qv = q2[b * HH + h * HD + d];
    const __half* kb = yk + (size_t)b * LY * HH + h * HD;
    const __half* vb = yv + (size_t)b * LY * HH + h * HD;
    for (int l = w; l < LY; l += 8) {
        float s = warpReduceSum(qv * __half2float(kb[(size_t)l * HH + d])) * scale;
        if (d == 0) sc[l] = s;
    }
    __syncthreads();
    float m = -3.4e38f;
    for (int l = t; l < LY; l += 256) m = fmaxf(m, sc[l]);
#pragma unroll
    for (int o = 16; o > 0; o >>= 1) m = fmaxf(m, __shfl_xor_sync(0xffffffffu, m, o));
    if (d == 0) red[w] = m;
    __syncthreads();
    float mm = red[0];
#pragma unroll
    for (int i = 1; i < 8; i++) mm = fmaxf(mm, red[i]);
    __syncthreads();
    float ssum = 0.f;
    for (int l = t; l < LY; l += 256) { float e = expf(sc[l] - mm); sc[l] = e; ssum += e; }
    ssum = warpReduceSum(ssum);
    if (d == 0) red[w] = ssum;
    __syncthreads();
    float tot = 0.f;
#pragma unroll
    for (int i = 0; i < 8; i++) tot += red[i];
    float acc = 0.f;
    for (int l = w; l < LY; l += 8) acc += sc[l] * __half2float(vb[(size_t)l * HH + d]);
    part[w][d] = acc;
    __syncthreads();
    if (w == 0) {
        float o = 0.f;
#pragma unroll
        for (int i = 0; i < 8; i++) o += part[i][d];
        att2[b * HH + h * HD + d] = o / tot;
    }
}

// ---------------- final: 0.5*max_l(nodes) + 0.5*relay ----------------
__global__ void __launch_bounds__(256)
final_kernel(const float* __restrict__ nodes, const float* __restrict__ relay,
             float* __restrict__ out)
{
    int b = blockIdx.x;
    int tx = threadIdx.x & 63, ty = threadIdx.x >> 6;
    float4 m = make_float4(-3.4e38f, -3.4e38f, -3.4e38f, -3.4e38f);
    for (int l = ty; l < LL; l += 4) {
        float4 v = *(const float4*)&nodes[(size_t)(b * LL + l) * HH + tx * 4];
        m.x = fmaxf(m.x, v.x); m.y = fmaxf(m.y, v.y);
        m.z = fmaxf(m.z, v.z); m.w = fmaxf(m.w, v.w);
    }
    __shared__ float4 part[4][64];
    part[ty][tx] = m;
    __syncthreads();
    if (ty == 0) {
        float4 s = part[0][tx];
#pragma unroll
        for (int i = 1; i < 4; i++) {
            s.x = fmaxf(s.x, part[i][tx].x); s.y = fmaxf(s.y, part[i][tx].y);
            s.z = fmaxf(s.z, part[i][tx].z); s.w = fmaxf(s.w, part[i][tx].w);
        }
        float4 r = *(const float4*)&relay[b * HH + tx * 4];
        *(float4*)&out[b * HH + tx * 4] =
            make_float4(0.5f * s.x + 0.5f * r.x, 0.5f * s.y + 0.5f * r.y,
                        0.5f * s.z + 0.5f * r.z, 0.5f * s.w + 0.5f * r.w);
    }
}

// ---------------- host ----------------
extern "C" void kernel_launch(void* const* d_in, const int* in_sizes, int n_in,
                              void* d_out, int out_size)
{
    const int*   data     = (const int*)  d_in[0];
    const float* emb      = (const float*)d_in[1];
    const float* emb_fc_W = (const float*)d_in[2];
    const float* emb_fc_b = (const float*)d_in[3];
    const float* pos_emb  = (const float*)d_in[4];
    const float* ln_g     = (const float*)d_in[5];
    const float* ln_b     = (const float*)d_in[6];
    const float* r_WQ = (const float*)d_in[7];
    const float* r_bQ = (const float*)d_in[8];
    const float* r_WK = (const float*)d_in[9];
    const float* r_bK = (const float*)d_in[10];
    const float* r_WV = (const float*)d_in[11];
    const float* r_bV = (const float*)d_in[12];
    const float* r_WO = (const float*)d_in[13];
    const float* r_bO = (const float*)d_in[14];
    const float* s_WQ = (const float*)d_in[15];
    const float* s_bQ = (const float*)d_in[16];
    const float* s_WK = (const float*)d_in[17];
    const float* s_bK = (const float*)d_in[18];
    const float* s_WV = (const float*)d_in[19];
    const float* s_bV = (const float*)d_in[20];
    const float* s_WO = (const float*)d_in[21];
    const float* s_bO = (const float*)d_in[22];
    float* out = (float*)d_out;
    (void)in_sizes; (void)n_in; (void)out_size;

    float *nodes, *relay, *ak, *av, *q2, *att2;
    __half *q16, *k16, *yk16, *yv16;
    __half *w16h, *w16l, *wEh, *wEl, *nln16, *att16, *y16;
    cudaGetSymbolAddress((void**)&nodes, g_nodes);
    cudaGetSymbolAddress((void**)&relay, g_relay);
    cudaGetSymbolAddress((void**)&ak,    g_ak);
    cudaGetSymbolAddress((void**)&av,    g_av);
    cudaGetSymbolAddress((void**)&q2,    g_q2);
    cudaGetSymbolAddress((void**)&att2,  g_att2);
    cudaGetSymbolAddress((void**)&q16,   g_q16);
    cudaGetSymbolAddress((void**)&k16,   g_k16);
    cudaGetSymbolAddress((void**)&yk16,  g_yk16);
    cudaGetSymbolAddress((void**)&yv16,  g_yv16);
    cudaGetSymbolAddress((void**)&w16h,  g_w16h);
    cudaGetSymbolAddress((void**)&w16l,  g_w16l);
    cudaGetSymbolAddress((void**)&wEh,   g_wEh);
    cudaGetSymbolAddress((void**)&wEl,   g_wEl);
    cudaGetSymbolAddress((void**)&nln16, g_nln16);
    cudaGetSymbolAddress((void**)&att16, g_att16);
    cudaGetSymbolAddress((void**)&y16,   g_y16);

    const int M1 = BB * LL;    // 16384
    const int M2 = BB * LY;    // 16416
    const int MMA_SMEM  = 98304;   // 2 x 48KB stages -> 2 blocks/SM
    const int EMB_SMEM  = 65536;
    static int attr_done = 0;
    if (!attr_done) {
        cudaFuncSetAttribute(gemm_mma_kernel,
                             cudaFuncAttributeMaxDynamicSharedMemorySize, MMA_SMEM);
        cudaFuncSetAttribute(gemm_emb_mma_kernel,
                             cudaFuncAttributeMaxDynamicSharedMemorySize, EMB_SMEM);
        attr_done = 1;
    }

    dim3 blk(256);
    auto WHp = [&](int slot) { return w16h + (size_t)slot * 65536; };
    auto WLp = [&](int slot) { return w16l + (size_t)slot * 65536; };

    // prep split-transposed weights (Q=0..5, K=6..11, O=12..17, sK=18..23, sV=24..29, emb=30)
    prep_w_kernel<<<dim3(8, 10, 31), dim3(32, 8)>>>(r_WQ, r_WK, r_WO, s_WK, s_WV, emb_fc_W,
                                                    w16h, w16l, wEh, wEl);

    // x0 = emb[data] @ emb_fc_W + b + pos ; relay = mean_L(x0)
    gemm_emb_mma_kernel<<<dim3(2, 128), blk, EMB_SMEM>>>(data, emb, wEh, wEl,
                                                         emb_fc_b, pos_emb, nodes);
    relay_mean_kernel<<<BB, blk>>>(nodes, relay);

    for (int i = 0; i < ITERS; i++) {
        const float* bQ = r_bQ + i * HH;
        const float* bK = r_bK + i * HH;
        const float* WK = r_WK + i * HH * HH;
        const float* WV = r_WV + i * HH * HH;
        const float* bV = r_bV + i * HH;
        const float* bO = r_bO + i * HH;
        const float* sWQ = s_WQ + i * HH * HH; const float* sbQ = s_bQ + i * HH;
        const float* sbK = s_bK + i * HH;
        const float* sbV = s_bV + i * HH;
        const float* sWO = s_WO + i * HH * HH; const float* sbO = s_bO + i * HH;

        // fused layernorm + (ak, av, q2, relay->y row)
        ln_rp4_kernel<<<2048 + 128, blk>>>(nodes, nln16, ln_g + i * HH, ln_b + i * HH,
                                           relay, WK, bK, ak, WV, bV, av,
                                           sWQ, sbQ, q2, y16);
        // fused Q + K projections (fp16 out)
        gemm_mma_kernel<<<dim3(2, 128, 2), blk, MMA_SMEM>>>(
            nln16, WHp(i), WLp(i), bQ, q16, WHp(6 + i), WLp(6 + i), bK, k16,
            M1, 0, nullptr, nullptr);
        msa1_attn_kernel<<<M1 / 8, blk>>>(q16, k16, ak, av, att16);
        // O projection + leaky residual + mask + y emit
        gemm_mma_kernel<<<dim3(2, 128, 1), blk, MMA_SMEM>>>(
            att16, WHp(12 + i), WLp(12 + i), bO, nodes,
            nullptr, nullptr, nullptr, nullptr,
            M1, 2, data, y16);
        // fused yK + yV (fp16 out)
        gemm_mma_kernel<<<dim3(2, 129, 2), blk, MMA_SMEM>>>(
            y16, WHp(18 + i), WLp(18 + i), sbK, yk16,
            WHp(24 + i), WLp(24 + i), sbV, yv16,
            M2, 0, nullptr, nullptr);
        msa2_attn_kernel<<<BB * NH, blk>>>(q2, yk16, yv16, att2);
        rowproj_kernel<<<BB, HH>>>(att2, sWO, sbO, relay, 1);
    }
    final_kernel<<<BB, blk>>>(nodes, relay, out);
}